// round 1
// baseline (speedup 1.0000x reference)
#include <cuda_runtime.h>
#include <cuda_bf16.h>
#include <math.h>

// Problem constants (fixed shapes for this dataset)
#define NN 50000
#define EE 800000
#define CC 128
#define HH 8
#define TT 8

// ---------------- scratch (device globals; no allocation allowed) -------------
__device__ float g_q[(size_t)NN * CC];
__device__ float g_k[(size_t)NN * CC];
__device__ float g_v[(size_t)NN * CC];
__device__ float g_vt[(size_t)TT * NN * CC];        // 204.8 MB
__device__ float g_escore[(size_t)EE * HH];
__device__ float g_den[(size_t)NN * HH];
__device__ float g_wv[(size_t)NN * CC];
__device__ float g_feat1[(size_t)NN * CC];
__device__ float g_hnorm[(size_t)NN * CC];
__device__ float g_hmid[(size_t)NN * 4 * CC];       // 102.4 MB

// ---------------- generic tiled linear: out = act(X@W + b) (+res) -------------
// X: M x kTot (ld ldx), W: kTot x (>=wcol0+128) (ld ldw), 128 output cols per launch.
// Tile: 64 rows x 128 cols, 256 threads, 96KB dynamic smem.
#define TILE_M 64

__global__ void lin128_kernel(
    const float* __restrict__ X, int ldx, int kTot,
    const float* __restrict__ W, int ldw, int wcol0,
    const float* __restrict__ bias,     // nullable; indexed [wcol0 + j]
    const float* __restrict__ res,      // nullable; ld = 128, col offset 0
    float* __restrict__ out, int ldo, int ocol0,
    int M, int doGelu)
{
    extern __shared__ float smem[];
    float* ws = smem;              // 128 x 128
    float* xs = smem + 128 * 128;  // 64 x 128

    const int tid  = threadIdx.x;
    const int lane = tid & 31;
    const int warp = tid >> 5;
    const int row0 = blockIdx.x * TILE_M;
    const int j4   = lane << 2;

    float acc[8][4];
#pragma unroll
    for (int r = 0; r < 8; r++)
#pragma unroll
        for (int j = 0; j < 4; j++) acc[r][j] = 0.0f;

    const int nChunks = kTot >> 7;
    for (int kc = 0; kc < nChunks; kc++) {
        // load W chunk (128x128)
#pragma unroll
        for (int i = 0; i < 16; i++) {
            int idx4 = tid + i * 256;          // float4 index (0..4095)
            int k = idx4 >> 5;
            int j = (idx4 & 31) << 2;
            *(float4*)&ws[k * 128 + j] =
                *(const float4*)&W[(size_t)(kc * 128 + k) * ldw + wcol0 + j];
        }
        // load X tile (64x128)
#pragma unroll
        for (int i = 0; i < 8; i++) {
            int idx4 = tid + i * 256;
            int r = idx4 >> 5;
            int c = (idx4 & 31) << 2;
            int row = row0 + r;
            float4 val = make_float4(0.f, 0.f, 0.f, 0.f);
            if (row < M)
                val = *(const float4*)&X[(size_t)row * ldx + kc * 128 + c];
            *(float4*)&xs[r * 128 + c] = val;
        }
        __syncthreads();

#pragma unroll 4
        for (int k = 0; k < 128; k++) {
            float4 w4 = *(float4*)&ws[k * 128 + j4];
#pragma unroll
            for (int rr = 0; rr < 8; rr++) {
                float xv = xs[(warp + rr * 8) * 128 + k];
                acc[rr][0] += xv * w4.x;
                acc[rr][1] += xv * w4.y;
                acc[rr][2] += xv * w4.z;
                acc[rr][3] += xv * w4.w;
            }
        }
        __syncthreads();
    }

    float b0 = 0.f, b1 = 0.f, b2 = 0.f, b3 = 0.f;
    if (bias) {
        float4 bb = *(const float4*)&bias[wcol0 + j4];
        b0 = bb.x; b1 = bb.y; b2 = bb.z; b3 = bb.w;
    }
#pragma unroll
    for (int rr = 0; rr < 8; rr++) {
        int row = row0 + warp + rr * 8;
        if (row >= M) continue;
        float v0 = acc[rr][0] + b0;
        float v1 = acc[rr][1] + b1;
        float v2 = acc[rr][2] + b2;
        float v3 = acc[rr][3] + b3;
        if (doGelu) {
            v0 = 0.5f * v0 * (1.0f + erff(v0 * 0.70710678118654752f));
            v1 = 0.5f * v1 * (1.0f + erff(v1 * 0.70710678118654752f));
            v2 = 0.5f * v2 * (1.0f + erff(v2 * 0.70710678118654752f));
            v3 = 0.5f * v3 * (1.0f + erff(v3 * 0.70710678118654752f));
        }
        if (res) {
            float4 rv = *(const float4*)&res[(size_t)row * 128 + j4];
            v0 += rv.x; v1 += rv.y; v2 += rv.z; v3 += rv.w;
        }
        float4 o = make_float4(v0, v1, v2, v3);
        *(float4*)&out[(size_t)row * ldo + ocol0 + j4] = o;
    }
}

// ---------------- zero kernel -------------------------------------------------
__global__ void zero_kernel(float* __restrict__ p, size_t n) {
    size_t i = (size_t)blockIdx.x * blockDim.x + threadIdx.x;
    size_t stride = (size_t)gridDim.x * blockDim.x;
    for (; i < n; i += stride) p[i] = 0.0f;
}

// ---------------- edge scores: exp(clip(q[dst].k[src]/4)) + den accumulation --
__global__ void score_kernel(
    const float* __restrict__ q, const float* __restrict__ k,
    const int* __restrict__ src, const int* __restrict__ dst,
    float* __restrict__ escore, float* __restrict__ den, int E)
{
    long idx = (long)blockIdx.x * blockDim.x + threadIdx.x;
    if (idx >= (long)E * HH) return;
    int e = (int)(idx >> 3);
    int h = (int)(idx & 7);
    int s = src[e], d = dst[e];
    const float4* qp = (const float4*)&q[(size_t)d * CC + h * 16];
    const float4* kp = (const float4*)&k[(size_t)s * CC + h * 16];
    float acc = 0.f;
#pragma unroll
    for (int i = 0; i < 4; i++) {
        float4 a = qp[i], b = kp[i];
        acc += a.x * b.x + a.y * b.y + a.z * b.z + a.w * b.w;
    }
    acc *= 0.25f;                         // 1/sqrt(16)
    acc = fminf(fmaxf(acc, -10.0f), 10.0f);
    float ex = expf(acc);
    escore[idx] = ex;
    atomicAdd(&den[(size_t)d * HH + h], ex);
}

// ---------------- edge aggregation: wv[dst] += alpha * (vt[etype,src] - efeat) -
__global__ void agg_kernel(
    const float* __restrict__ vt, const float* __restrict__ efeat,
    const float* __restrict__ escore, const float* __restrict__ den,
    const int* __restrict__ src, const int* __restrict__ dst,
    const int* __restrict__ etype,
    float* __restrict__ wv, int E, int Nn)
{
    int e = (int)(((long)blockIdx.x * blockDim.x + threadIdx.x) >> 5);
    if (e >= E) return;
    int lane = threadIdx.x & 31;
    int s = src[e], d = dst[e], t = etype[e];
    int h = lane >> 2;
    float alpha = escore[(size_t)e * HH + h] / den[(size_t)d * HH + h];
    float4 vv = *(const float4*)&vt[((size_t)t * Nn + s) * CC + lane * 4];
    float4 ef = *(const float4*)&efeat[(size_t)e * CC + lane * 4];
    float m0 = (vv.x - ef.x) * alpha;
    float m1 = (vv.y - ef.y) * alpha;
    float m2 = (vv.z - ef.z) * alpha;
    float m3 = (vv.w - ef.w) * alpha;
    float* p = &wv[(size_t)d * CC + lane * 4];
    asm volatile("red.global.add.v4.f32 [%0], {%1, %2, %3, %4};"
                 :: "l"(p), "f"(m0), "f"(m1), "f"(m2), "f"(m3) : "memory");
}

// ---------------- layernorm (warp per row) ------------------------------------
__global__ void ln_kernel(
    const float* __restrict__ x, const float* __restrict__ g,
    const float* __restrict__ b, float* __restrict__ out, int M)
{
    int row = (int)(((long)blockIdx.x * blockDim.x + threadIdx.x) >> 5);
    if (row >= M) return;
    int lane = threadIdx.x & 31;
    float4 v = *(const float4*)&x[(size_t)row * CC + lane * 4];
    float s = v.x + v.y + v.z + v.w;
#pragma unroll
    for (int o = 16; o > 0; o >>= 1) s += __shfl_xor_sync(0xffffffffu, s, o);
    float mu = s * (1.0f / 128.0f);
    float d0 = v.x - mu, d1 = v.y - mu, d2 = v.z - mu, d3 = v.w - mu;
    float ss = d0 * d0 + d1 * d1 + d2 * d2 + d3 * d3;
#pragma unroll
    for (int o = 16; o > 0; o >>= 1) ss += __shfl_xor_sync(0xffffffffu, ss, o);
    float inv = rsqrtf(ss * (1.0f / 128.0f) + 1e-5f);
    float4 gg = *(const float4*)&g[lane * 4];
    float4 bb = *(const float4*)&b[lane * 4];
    float4 o4 = make_float4(d0 * inv * gg.x + bb.x,
                            d1 * inv * gg.y + bb.y,
                            d2 * inv * gg.z + bb.z,
                            d3 * inv * gg.w + bb.w);
    *(float4*)&out[(size_t)row * CC + lane * 4] = o4;
}

// ---------------- host side ----------------------------------------------------
static inline void launch_lin(const float* X, int ldx, int kTot,
                              const float* W, int ldw, int wcol0,
                              const float* bias, const float* res,
                              float* out, int ldo, int ocol0,
                              int M, int doGelu)
{
    dim3 grid((M + TILE_M - 1) / TILE_M);
    lin128_kernel<<<grid, 256, 98304>>>(X, ldx, kTot, W, ldw, wcol0,
                                        bias, res, out, ldo, ocol0, M, doGelu);
}

extern "C" void kernel_launch(void* const* d_in, const int* in_sizes, int n_in,
                              void* d_out, int out_size)
{
    const float* feat  = (const float*)d_in[0];
    const float* efeat = (const float*)d_in[1];
    const int*   src   = (const int*)d_in[2];
    const int*   dst   = (const int*)d_in[3];
    const int*   etype = (const int*)d_in[4];

    int base = 5;
    if (in_sizes[5] == 1) base = 6;   // skip scalar n_head if present as input

    const float* Wq    = (const float*)d_in[base + 0];
    const float* bq    = (const float*)d_in[base + 1];
    const float* Wk    = (const float*)d_in[base + 2];
    const float* bk    = (const float*)d_in[base + 3];
    const float* Wv    = (const float*)d_in[base + 4];
    const float* bv    = (const float*)d_in[base + 5];
    const float* W_rel = (const float*)d_in[base + 6];
    const float* Wproj = (const float*)d_in[base + 7];
    const float* bproj = (const float*)d_in[base + 8];
    const float* WeW   = (const float*)d_in[base + 9];
    const float* beW   = (const float*)d_in[base + 10];
    const float* ln_g  = (const float*)d_in[base + 11];
    const float* ln_b  = (const float*)d_in[base + 12];
    const float* W1    = (const float*)d_in[base + 13];
    const float* b1    = (const float*)d_in[base + 14];
    const float* W2    = (const float*)d_in[base + 15];
    const float* b2    = (const float*)d_in[base + 16];

    const int N = in_sizes[0] / CC;
    const int E = in_sizes[1] / CC;

    float *q, *k, *v, *vt, *esc, *den, *wv, *feat1, *hn, *hmid;
    cudaGetSymbolAddress((void**)&q,     g_q);
    cudaGetSymbolAddress((void**)&k,     g_k);
    cudaGetSymbolAddress((void**)&v,     g_v);
    cudaGetSymbolAddress((void**)&vt,    g_vt);
    cudaGetSymbolAddress((void**)&esc,   g_escore);
    cudaGetSymbolAddress((void**)&den,   g_den);
    cudaGetSymbolAddress((void**)&wv,    g_wv);
    cudaGetSymbolAddress((void**)&feat1, g_feat1);
    cudaGetSymbolAddress((void**)&hn,    g_hnorm);
    cudaGetSymbolAddress((void**)&hmid,  g_hmid);

    cudaFuncSetAttribute(lin128_kernel,
                         cudaFuncAttributeMaxDynamicSharedMemorySize, 98304);

    float* out_feat  = (float*)d_out;
    float* out_efeat = (float*)d_out + (size_t)N * CC;

    // 0) zero accumulators
    zero_kernel<<<1024, 256>>>(den, (size_t)N * HH);
    zero_kernel<<<1024, 256>>>(wv,  (size_t)N * CC);

    // 1) q, k, v projections
    launch_lin(feat, CC, CC, Wq, CC, 0, bq, nullptr, q, CC, 0, N, 0);
    launch_lin(feat, CC, CC, Wk, CC, 0, bk, nullptr, k, CC, 0, N, 0);
    launch_lin(feat, CC, CC, Wv, CC, 0, bv, nullptr, v, CC, 0, N, 0);

    // 2) vt[t] = v @ W_rel[t]
    for (int t = 0; t < TT; t++) {
        launch_lin(v, CC, CC, W_rel + (size_t)t * CC * CC, CC, 0,
                   nullptr, nullptr, vt + (size_t)t * N * CC, CC, 0, N, 0);
    }

    // 3) edge scores + softmax denominators (max-free: scores clipped to +-10)
    {
        long total = (long)E * HH;
        int blocks = (int)((total + 255) / 256);
        score_kernel<<<blocks, 256>>>(q, k, src, dst, esc, den, E);
    }

    // 4) edge aggregation into wv
    {
        long total = (long)E * 32;
        int blocks = (int)((total + 255) / 256);
        agg_kernel<<<blocks, 256>>>(vt, efeat, esc, den, src, dst, etype,
                                    wv, E, N);
    }

    // 5) feat1 = feat + wv @ Wproj + bproj
    launch_lin(wv, CC, CC, Wproj, CC, 0, bproj, feat, feat1, CC, 0, N, 0);

    // 6) hnorm = layernorm(feat1)
    {
        long total = (long)N * 32;
        int blocks = (int)((total + 255) / 256);
        ln_kernel<<<blocks, 256>>>(feat1, ln_g, ln_b, hn, N);
    }

    // 7) hmid = gelu(hnorm @ W1 + b1)   (4 column chunks of 128)
    for (int cchunk = 0; cchunk < 4; cchunk++) {
        launch_lin(hn, CC, CC, W1, 4 * CC, cchunk * CC, b1, nullptr,
                   hmid, 4 * CC, cchunk * CC, N, 1);
    }

    // 8) feat_out = feat1 + hmid @ W2 + b2
    launch_lin(hmid, 4 * CC, 4 * CC, W2, CC, 0, b2, feat1,
               out_feat, CC, 0, N, 0);

    // 9) efeat_out = efeat @ WeW + beW
    launch_lin(efeat, CC, CC, WeW, CC, 0, beW, nullptr,
               out_efeat, CC, 0, E, 0);
}

// round 3
// speedup vs baseline: 2.0014x; 2.0014x over previous
#include <cuda_runtime.h>
#include <cuda_bf16.h>
#include <math.h>
#include <stdint.h>

// Problem constants
#define NN 50000
#define EE 800000
#define CC 128
#define HH 8
#define TT 8

// ---------------- scratch (device globals) -------------------------------------
__device__ float g_q[(size_t)NN * CC];
__device__ float g_k[(size_t)NN * CC];
__device__ float g_v[(size_t)NN * CC];
__device__ float g_vt[(size_t)TT * NN * CC];
__device__ float g_escore[(size_t)EE * HH];
__device__ float g_den[(size_t)NN * HH];
__device__ float g_wv[(size_t)NN * CC];
__device__ float g_feat1[(size_t)NN * CC];
__device__ float g_hnorm[(size_t)NN * CC];
__device__ float g_hmid[(size_t)NN * 4 * CC];

// ---------------- warp-MMA helpers ----------------------------------------------
__device__ __forceinline__ uint32_t smem_u32(const void* p) {
    uint32_t addr;
    asm("{ .reg .u64 t; cvta.to.shared.u64 t, %1; cvt.u32.u64 %0, t; }"
        : "=r"(addr) : "l"(p));
    return addr;
}

__device__ __forceinline__ void ldsm_x4(uint32_t* r, uint32_t addr) {
    asm volatile("ldmatrix.sync.aligned.m8n8.x4.shared.b16 {%0,%1,%2,%3}, [%4];"
                 : "=r"(r[0]), "=r"(r[1]), "=r"(r[2]), "=r"(r[3]) : "r"(addr));
}
__device__ __forceinline__ void ldsm_x4_t(uint32_t* r, uint32_t addr) {
    asm volatile("ldmatrix.sync.aligned.m8n8.x4.trans.shared.b16 {%0,%1,%2,%3}, [%4];"
                 : "=r"(r[0]), "=r"(r[1]), "=r"(r[2]), "=r"(r[3]) : "r"(addr));
}
__device__ __forceinline__ void mma16816(float* c, const uint32_t* a, const uint32_t* b) {
    asm volatile(
        "mma.sync.aligned.m16n8k16.row.col.f32.bf16.bf16.f32 "
        "{%0,%1,%2,%3}, {%4,%5,%6,%7}, {%8,%9}, {%0,%1,%2,%3};"
        : "+f"(c[0]), "+f"(c[1]), "+f"(c[2]), "+f"(c[3])
        : "r"(a[0]), "r"(a[1]), "r"(a[2]), "r"(a[3]), "r"(b[0]), "r"(b[1]));
}

// ---------------- tensor-core GEMM: out = act(X@W + b) (+res) --------------------
// CTA: 128 rows x 128 cols. K processed in chunks of 64.
// bf16 3-split: D = Ah@Bh + Ah@Bl + Al@Bh, fp32 accumulation in registers.
// smem: A tiles [128][64] bf16 (hi, lo), 128B rows; B tiles [64][128] bf16 (hi, lo),
// 256B rows, both XOR-swizzled for conflict-free ldmatrix.
#define SA_H 0
#define SA_L 16384
#define SB_H 32768
#define SB_L 49152
#define SM_TOTAL 65536

__global__ void __launch_bounds__(256, 2) gemm_mma_kernel(
    const float* __restrict__ X, int ldx, int kTot,
    const float* __restrict__ W, int ldw,
    const float* __restrict__ bias,   // nullable, indexed [wcol0 + c]
    const float* __restrict__ res,    // nullable, ld = 128, local cols
    float* __restrict__ out, int ldo,
    int M, int doGelu)
{
    extern __shared__ char smem[];
    const uint32_t sb = smem_u32(smem);
    const int tid  = threadIdx.x;
    const int wid  = tid >> 5;
    const int lane = tid & 31;
    const int wm   = wid & 1;        // warp row (2)
    const int wn   = wid >> 1;       // warp col (4)
    const int row0  = blockIdx.x * 128;
    const int wcol0 = blockIdx.y * 128;

    float acc[4][4][4];
#pragma unroll
    for (int i = 0; i < 4; i++)
#pragma unroll
        for (int j = 0; j < 4; j++)
#pragma unroll
            for (int l = 0; l < 4; l++) acc[i][j][l] = 0.0f;

    // precomputed ldmatrix lane addresses (byte offsets within tiles)
    // A: rows = wm*64 + mf*16 + (lane&15), k chunk = (lane>>4)*8
    const int a_r  = wm * 64 + (lane & 15);
    const int a_k8 = (lane >> 4) << 3;
    // B: k = ((lane>>3)&1)*8 + (lane&7), n = wn*32 + pair*16 + (lane>>4)*8
    const int b_k  = (((lane >> 3) & 1) << 3) + (lane & 7);
    const int b_n  = wn * 32 + ((lane >> 4) << 3);

    const int nChunks = kTot >> 6;
    for (int kc = 0; kc < nChunks; kc++) {
        __syncthreads();
        // ---- load & convert A tile: 128 rows x 64 k (float2 per iter) ----
#pragma unroll
        for (int it = 0; it < 16; it++) {
            int idx = tid + it * 256;          // 0..4095 float2
            int r  = idx >> 5;
            int k  = (idx & 31) << 1;
            int row = row0 + r;
            float2 x = make_float2(0.f, 0.f);
            if (row < M)
                x = *(const float2*)&X[(size_t)row * ldx + kc * 64 + k];
            __nv_bfloat162 hi = __floats2bfloat162_rn(x.x, x.y);
            float lx = x.x - __bfloat162float(__low2bfloat16(hi));
            float ly = x.y - __bfloat162float(__high2bfloat16(hi));
            __nv_bfloat162 lo = __floats2bfloat162_rn(lx, ly);
            uint32_t byte = (uint32_t)r * 128u + (((uint32_t)k * 2u) ^ ((r & 7) << 4));
            *(__nv_bfloat162*)(smem + SA_H + byte) = hi;
            *(__nv_bfloat162*)(smem + SA_L + byte) = lo;
        }
        // ---- load & convert B tile: [k][n] = W[kc*64+k][wcol0+n], 64 x 128 ----
#pragma unroll
        for (int it = 0; it < 16; it++) {
            int idx = tid + it * 256;          // 0..4095 float2
            int k  = idx >> 6;
            int n  = (idx & 63) << 1;
            float2 x = *(const float2*)&W[(size_t)(kc * 64 + k) * ldw + wcol0 + n];
            __nv_bfloat162 hi = __floats2bfloat162_rn(x.x, x.y);
            float lx = x.x - __bfloat162float(__low2bfloat16(hi));
            float ly = x.y - __bfloat162float(__high2bfloat16(hi));
            __nv_bfloat162 lo = __floats2bfloat162_rn(lx, ly);
            uint32_t byte = (uint32_t)k * 256u + (((uint32_t)n * 2u) ^ ((k & 7) << 4));
            *(__nv_bfloat162*)(smem + SB_H + byte) = hi;
            *(__nv_bfloat162*)(smem + SB_L + byte) = lo;
        }
        __syncthreads();

        // ---- 4 k-steps of 16 ----
#pragma unroll
        for (int ks = 0; ks < 4; ks++) {
            const int k0 = ks * 16;

            // B fragments (hi and lo), 4 n-frags each
            uint32_t bh[4][2], bl[4][2];
            {
                int kk = k0 + b_k;
                uint32_t bswz = (uint32_t)kk * 256u;
#pragma unroll
                for (int pair = 0; pair < 2; pair++) {
                    int n = b_n + pair * 16;
                    uint32_t byte = bswz + (((uint32_t)n * 2u) ^ ((kk & 7) << 4));
                    uint32_t r[4];
                    ldsm_x4_t(r, sb + SB_H + byte);
                    bh[2 * pair][0] = r[0]; bh[2 * pair][1] = r[1];
                    bh[2 * pair + 1][0] = r[2]; bh[2 * pair + 1][1] = r[3];
                    ldsm_x4_t(r, sb + SB_L + byte);
                    bl[2 * pair][0] = r[0]; bl[2 * pair][1] = r[1];
                    bl[2 * pair + 1][0] = r[2]; bl[2 * pair + 1][1] = r[3];
                }
            }

            // A hi fragments: 4 m-frags
            uint32_t a[4][4];
            {
                int kk = k0 + a_k8;
#pragma unroll
                for (int mf = 0; mf < 4; mf++) {
                    int r = a_r + mf * 16;
                    uint32_t byte = (uint32_t)r * 128u + (((uint32_t)kk * 2u) ^ ((r & 7) << 4));
                    ldsm_x4(a[mf], sb + SA_H + byte);
                }
            }
            // Ah @ Bh and Ah @ Bl
#pragma unroll
            for (int mf = 0; mf < 4; mf++)
#pragma unroll
                for (int nf = 0; nf < 4; nf++) {
                    mma16816(acc[mf][nf], a[mf], bh[nf]);
                    mma16816(acc[mf][nf], a[mf], bl[nf]);
                }

            // A lo fragments (reuse regs)
            {
                int kk = k0 + a_k8;
#pragma unroll
                for (int mf = 0; mf < 4; mf++) {
                    int r = a_r + mf * 16;
                    uint32_t byte = (uint32_t)r * 128u + (((uint32_t)kk * 2u) ^ ((r & 7) << 4));
                    ldsm_x4(a[mf], sb + SA_L + byte);
                }
            }
            // Al @ Bh
#pragma unroll
            for (int mf = 0; mf < 4; mf++)
#pragma unroll
                for (int nf = 0; nf < 4; nf++)
                    mma16816(acc[mf][nf], a[mf], bh[nf]);
        }
    }

    // ---- epilogue ----
    const int g = lane >> 2;            // 0..7
    const int t = lane & 3;             // 0..3
#pragma unroll
    for (int mf = 0; mf < 4; mf++) {
#pragma unroll
        for (int nf = 0; nf < 4; nf++) {
            int cl = wn * 32 + nf * 8 + 2 * t;        // local col (0..127)
            float b0 = 0.f, b1 = 0.f;
            if (bias) { b0 = bias[wcol0 + cl]; b1 = bias[wcol0 + cl + 1]; }
#pragma unroll
            for (int half = 0; half < 2; half++) {
                int r = row0 + wm * 64 + mf * 16 + g + half * 8;
                if (r >= M) continue;
                float v0 = acc[mf][nf][2 * half]     + b0;
                float v1 = acc[mf][nf][2 * half + 1] + b1;
                if (doGelu) {
                    v0 = 0.5f * v0 * (1.0f + erff(v0 * 0.70710678118654752f));
                    v1 = 0.5f * v1 * (1.0f + erff(v1 * 0.70710678118654752f));
                }
                if (res) {
                    float2 rv = *(const float2*)&res[(size_t)r * 128 + cl];
                    v0 += rv.x; v1 += rv.y;
                }
                *(float2*)&out[(size_t)r * ldo + wcol0 + cl] = make_float2(v0, v1);
            }
        }
    }
}

// ---------------- zero kernel ----------------------------------------------------
__global__ void zero_kernel(float* __restrict__ p, size_t n) {
    size_t i = (size_t)blockIdx.x * blockDim.x + threadIdx.x;
    size_t stride = (size_t)gridDim.x * blockDim.x;
    for (; i < n; i += stride) p[i] = 0.0f;
}

// ---------------- edge scores + softmax denominators ------------------------------
__global__ void score_kernel(
    const float* __restrict__ q, const float* __restrict__ k,
    const int* __restrict__ src, const int* __restrict__ dst,
    float* __restrict__ escore, float* __restrict__ den, int E)
{
    long idx = (long)blockIdx.x * blockDim.x + threadIdx.x;
    if (idx >= (long)E * HH) return;
    int e = (int)(idx >> 3);
    int h = (int)(idx & 7);
    int s = src[e], d = dst[e];
    const float4* qp = (const float4*)&q[(size_t)d * CC + h * 16];
    const float4* kp = (const float4*)&k[(size_t)s * CC + h * 16];
    float acc = 0.f;
#pragma unroll
    for (int i = 0; i < 4; i++) {
        float4 a = qp[i], b = kp[i];
        acc += a.x * b.x + a.y * b.y + a.z * b.z + a.w * b.w;
    }
    acc *= 0.25f;
    acc = fminf(fmaxf(acc, -10.0f), 10.0f);
    float ex = expf(acc);
    escore[idx] = ex;
    atomicAdd(&den[(size_t)d * HH + h], ex);
}

// ---------------- edge aggregation ------------------------------------------------
__global__ void agg_kernel(
    const float* __restrict__ vt, const float* __restrict__ efeat,
    const float* __restrict__ escore, const float* __restrict__ den,
    const int* __restrict__ src, const int* __restrict__ dst,
    const int* __restrict__ etype,
    float* __restrict__ wv, int E, int Nn)
{
    int e = (int)(((long)blockIdx.x * blockDim.x + threadIdx.x) >> 5);
    if (e >= E) return;
    int lane = threadIdx.x & 31;
    int s = src[e], d = dst[e], t = etype[e];
    int h = lane >> 2;
    float alpha = escore[(size_t)e * HH + h] / den[(size_t)d * HH + h];
    float4 vv = *(const float4*)&vt[((size_t)t * Nn + s) * CC + lane * 4];
    float4 ef = *(const float4*)&efeat[(size_t)e * CC + lane * 4];
    float m0 = (vv.x - ef.x) * alpha;
    float m1 = (vv.y - ef.y) * alpha;
    float m2 = (vv.z - ef.z) * alpha;
    float m3 = (vv.w - ef.w) * alpha;
    float* p = &wv[(size_t)d * CC + lane * 4];
    asm volatile("red.global.add.v4.f32 [%0], {%1, %2, %3, %4};"
                 :: "l"(p), "f"(m0), "f"(m1), "f"(m2), "f"(m3) : "memory");
}

// ---------------- layernorm --------------------------------------------------------
__global__ void ln_kernel(
    const float* __restrict__ x, const float* __restrict__ g,
    const float* __restrict__ b, float* __restrict__ out, int M)
{
    int row = (int)(((long)blockIdx.x * blockDim.x + threadIdx.x) >> 5);
    if (row >= M) return;
    int lane = threadIdx.x & 31;
    float4 v = *(const float4*)&x[(size_t)row * CC + lane * 4];
    float s = v.x + v.y + v.z + v.w;
#pragma unroll
    for (int o = 16; o > 0; o >>= 1) s += __shfl_xor_sync(0xffffffffu, s, o);
    float mu = s * (1.0f / 128.0f);
    float d0 = v.x - mu, d1 = v.y - mu, d2 = v.z - mu, d3 = v.w - mu;
    float ss = d0 * d0 + d1 * d1 + d2 * d2 + d3 * d3;
#pragma unroll
    for (int o = 16; o > 0; o >>= 1) ss += __shfl_xor_sync(0xffffffffu, ss, o);
    float inv = rsqrtf(ss * (1.0f / 128.0f) + 1e-5f);
    float4 gg = *(const float4*)&g[lane * 4];
    float4 bb = *(const float4*)&b[lane * 4];
    float4 o4 = make_float4(d0 * inv * gg.x + bb.x,
                            d1 * inv * gg.y + bb.y,
                            d2 * inv * gg.z + bb.z,
                            d3 * inv * gg.w + bb.w);
    *(float4*)&out[(size_t)row * CC + lane * 4] = o4;
}

// ---------------- host side ---------------------------------------------------------
static inline void launch_gemm(const float* X, int ldx, int kTot,
                               const float* W, int ldw,
                               const float* bias, const float* res,
                               float* out, int ldo,
                               int M, int nColChunks, int doGelu)
{
    dim3 grid((M + 127) / 128, nColChunks);
    gemm_mma_kernel<<<grid, 256, SM_TOTAL>>>(X, ldx, kTot, W, ldw, bias, res,
                                             out, ldo, M, doGelu);
}

extern "C" void kernel_launch(void* const* d_in, const int* in_sizes, int n_in,
                              void* d_out, int out_size)
{
    const float* feat  = (const float*)d_in[0];
    const float* efeat = (const float*)d_in[1];
    const int*   src   = (const int*)d_in[2];
    const int*   dst   = (const int*)d_in[3];
    const int*   etype = (const int*)d_in[4];

    int base = 5;
    if (in_sizes[5] == 1) base = 6;

    const float* Wq    = (const float*)d_in[base + 0];
    const float* bq    = (const float*)d_in[base + 1];
    const float* Wk    = (const float*)d_in[base + 2];
    const float* bk    = (const float*)d_in[base + 3];
    const float* Wv    = (const float*)d_in[base + 4];
    const float* bv    = (const float*)d_in[base + 5];
    const float* W_rel = (const float*)d_in[base + 6];
    const float* Wproj = (const float*)d_in[base + 7];
    const float* bproj = (const float*)d_in[base + 8];
    const float* WeW   = (const float*)d_in[base + 9];
    const float* beW   = (const float*)d_in[base + 10];
    const float* ln_g  = (const float*)d_in[base + 11];
    const float* ln_b  = (const float*)d_in[base + 12];
    const float* W1    = (const float*)d_in[base + 13];
    const float* b1    = (const float*)d_in[base + 14];
    const float* W2    = (const float*)d_in[base + 15];
    const float* b2    = (const float*)d_in[base + 16];

    const int N = in_sizes[0] / CC;
    const int E = in_sizes[1] / CC;

    float *q, *k, *v, *vt, *esc, *den, *wv, *feat1, *hn, *hmid;
    cudaGetSymbolAddress((void**)&q,     g_q);
    cudaGetSymbolAddress((void**)&k,     g_k);
    cudaGetSymbolAddress((void**)&v,     g_v);
    cudaGetSymbolAddress((void**)&vt,    g_vt);
    cudaGetSymbolAddress((void**)&esc,   g_escore);
    cudaGetSymbolAddress((void**)&den,   g_den);
    cudaGetSymbolAddress((void**)&wv,    g_wv);
    cudaGetSymbolAddress((void**)&feat1, g_feat1);
    cudaGetSymbolAddress((void**)&hn,    g_hnorm);
    cudaGetSymbolAddress((void**)&hmid,  g_hmid);

    cudaFuncSetAttribute(gemm_mma_kernel,
                         cudaFuncAttributeMaxDynamicSharedMemorySize, SM_TOTAL);

    float* out_feat  = (float*)d_out;
    float* out_efeat = (float*)d_out + (size_t)N * CC;

    // 0) zero accumulators
    zero_kernel<<<1024, 256>>>(den, (size_t)N * HH);
    zero_kernel<<<1024, 256>>>(wv,  (size_t)N * CC);

    // 1) q, k, v projections
    launch_gemm(feat, CC, CC, Wq, CC, bq, nullptr, q, CC, N, 1, 0);
    launch_gemm(feat, CC, CC, Wk, CC, bk, nullptr, k, CC, N, 1, 0);
    launch_gemm(feat, CC, CC, Wv, CC, bv, nullptr, v, CC, N, 1, 0);

    // 2) vt[t] = v @ W_rel[t]
    for (int t = 0; t < TT; t++) {
        launch_gemm(v, CC, CC, W_rel + (size_t)t * CC * CC, CC,
                    nullptr, nullptr, vt + (size_t)t * N * CC, CC, N, 1, 0);
    }

    // 3) edge scores + denominators (max-free: clipped to +-10)
    {
        long total = (long)E * HH;
        int blocks = (int)((total + 255) / 256);
        score_kernel<<<blocks, 256>>>(q, k, src, dst, esc, den, E);
    }

    // 4) edge aggregation
    {
        long total = (long)E * 32;
        int blocks = (int)((total + 255) / 256);
        agg_kernel<<<blocks, 256>>>(vt, efeat, esc, den, src, dst, etype,
                                    wv, E, N);
    }

    // 5) feat1 = feat + wv @ Wproj + bproj
    launch_gemm(wv, CC, CC, Wproj, CC, bproj, feat, feat1, CC, N, 1, 0);

    // 6) hnorm = layernorm(feat1)
    {
        long total = (long)N * 32;
        int blocks = (int)((total + 255) / 256);
        ln_kernel<<<blocks, 256>>>(feat1, ln_g, ln_b, hn, N);
    }

    // 7) hmid = gelu(hnorm @ W1 + b1)   (4 column chunks of 128 via grid.y)
    launch_gemm(hn, CC, CC, W1, 4 * CC, b1, nullptr, hmid, 4 * CC, N, 4, 1);

    // 8) feat_out = feat1 + hmid @ W2 + b2   (K = 512)
    launch_gemm(hmid, 4 * CC, 4 * CC, W2, CC, b2, feat1, out_feat, CC, N, 1, 0);

    // 9) efeat_out = efeat @ WeW + beW
    launch_gemm(efeat, CC, CC, WeW, CC, beW, nullptr, out_efeat, CC, E, 1, 0);
}

// round 5
// speedup vs baseline: 2.3786x; 1.1884x over previous
#include <cuda_runtime.h>
#include <cuda_bf16.h>
#include <math.h>
#include <stdint.h>

// Problem constants
#define NN 50000
#define EE 800000
#define CC 128
#define HH 8
#define TT 8

// ---------------- scratch (device globals) -------------------------------------
__device__ float g_qk[(size_t)2 * NN * CC];          // q then k
__device__ __nv_bfloat16 g_vhi[(size_t)NN * CC];
__device__ __nv_bfloat16 g_vlo[(size_t)NN * CC];
__device__ __nv_bfloat16 g_feathi[(size_t)NN * CC];
__device__ __nv_bfloat16 g_featlo[(size_t)NN * CC];
__device__ __nv_bfloat16 g_hnhi[(size_t)NN * CC];
__device__ __nv_bfloat16 g_hnlo[(size_t)NN * CC];
__device__ float g_vt[(size_t)TT * NN * CC];
__device__ float g_escore[(size_t)EE * HH];
__device__ float g_den[(size_t)NN * HH];
__device__ float g_wv[(size_t)NN * CC];
__device__ float g_feat1[(size_t)NN * CC];
__device__ float g_hmid[(size_t)NN * 4 * CC];

// bf16 pre-split weights, one big buffer each (hi / lo)
#define WOFF_Q    0
#define WOFF_K    16384
#define WOFF_V    32768
#define WOFF_REL  49152
#define WOFF_PROJ 180224
#define WOFF_EW   196608
#define WOFF_W1   212992
#define WOFF_W2   278528
#define WBF_TOTAL 344064
__device__ __nv_bfloat16 g_wbf_hi[WBF_TOTAL];
__device__ __nv_bfloat16 g_wbf_lo[WBF_TOTAL];

// ---------------- PTX helpers -----------------------------------------------------
__device__ __forceinline__ uint32_t __bfloat162_as_uint(__nv_bfloat162 v) {
    return *reinterpret_cast<uint32_t*>(&v);
}
__device__ __forceinline__ uint32_t smem_u32(const void* p) {
    uint32_t addr;
    asm("{ .reg .u64 t; cvta.to.shared.u64 t, %1; cvt.u32.u64 %0, t; }"
        : "=r"(addr) : "l"(p));
    return addr;
}
__device__ __forceinline__ void ldsm_x4(uint32_t* r, uint32_t addr) {
    asm volatile("ldmatrix.sync.aligned.m8n8.x4.shared.b16 {%0,%1,%2,%3}, [%4];"
                 : "=r"(r[0]), "=r"(r[1]), "=r"(r[2]), "=r"(r[3]) : "r"(addr));
}
__device__ __forceinline__ void ldsm_x4_t(uint32_t* r, uint32_t addr) {
    asm volatile("ldmatrix.sync.aligned.m8n8.x4.trans.shared.b16 {%0,%1,%2,%3}, [%4];"
                 : "=r"(r[0]), "=r"(r[1]), "=r"(r[2]), "=r"(r[3]) : "r"(addr));
}
__device__ __forceinline__ void mma16816(float* c, const uint32_t* a, const uint32_t* b) {
    asm volatile(
        "mma.sync.aligned.m16n8k16.row.col.f32.bf16.bf16.f32 "
        "{%0,%1,%2,%3}, {%4,%5,%6,%7}, {%8,%9}, {%0,%1,%2,%3};"
        : "+f"(c[0]), "+f"(c[1]), "+f"(c[2]), "+f"(c[3])
        : "r"(a[0]), "r"(a[1]), "r"(a[2]), "r"(a[3]), "r"(b[0]), "r"(b[1]));
}
__device__ __forceinline__ void cp16(uint32_t dst, const void* src) {
    asm volatile("cp.async.cg.shared.global [%0], [%1], 16;"
                 :: "r"(dst), "l"(src) : "memory");
}
__device__ __forceinline__ void cp16z(uint32_t dst, const void* src, int bytes) {
    asm volatile("cp.async.cg.shared.global [%0], [%1], 16, %2;"
                 :: "r"(dst), "l"(src), "r"(bytes) : "memory");
}
__device__ __forceinline__ void cp_commit() {
    asm volatile("cp.async.commit_group;" ::: "memory");
}
__device__ __forceinline__ void cp_wait0() {
    asm volatile("cp.async.wait_group 0;" ::: "memory");
}

// smem tile swizzles
// A tile: 128 rows x 32 k bf16, 64B rows
__device__ __forceinline__ uint32_t a_swz(int r, int c16) {
    return (uint32_t)r * 64u + (uint32_t)((c16 ^ ((r >> 1) & 3)) << 4);
}
// B tile: 32 k-rows x 128 n bf16, 256B rows
__device__ __forceinline__ uint32_t b_swz(int k, int c16) {
    return (uint32_t)k * 256u + (uint32_t)((c16 ^ (k & 7)) << 4);
}

__device__ __forceinline__ float gelu1(float v) {
    return 0.5f * v * (1.0f + erff(v * 0.70710678118654752f));
}

// ---------------- pipelined bf16 tensor-core GEMM ---------------------------------
// CTA tile 128x128, K-chunk 32, double-buffered cp.async stages.
// 3-split: D = Ah@Bh + Ah@Bl + Al@Bh.
// A source: either fp32 (inline convert, reg-prefetched) or pre-split bf16 (cp.async).
// stage layout (32KB): Ahi @0, Alo @8K, Bhi @16K, Blo @24K;  stage1 @32K.
#define STG 32768
#define SA_HI 0
#define SA_LO 8192
#define SB_HI 16384
#define SB_LO 24576
#define SM_TOTAL 65536

__global__ void __launch_bounds__(256, 2) gemm_bf16_kernel(
    const float* __restrict__ Xf,                 // fp32 A (or null)
    const __nv_bfloat16* __restrict__ Ahi,        // bf16 A (or null)
    const __nv_bfloat16* __restrict__ Alo,
    int ldx, int kTot,
    const __nv_bfloat16* __restrict__ Bhi,        // pre-split weights
    const __nv_bfloat16* __restrict__ Blo,
    int ldw, size_t w_y_off, int col_y,
    const float* __restrict__ bias,               // nullable, [wcol0+c]
    const float* __restrict__ res,                // nullable, ld=128
    float* __restrict__ outF, int ldo, size_t out_y_off,
    __nv_bfloat16* __restrict__ outBhi,           // bf16 out mode (v)
    __nv_bfloat16* __restrict__ outBlo,
    int M, int doGelu)
{
    extern __shared__ char smem[];
    const uint32_t sb = smem_u32(smem);
    const int tid  = threadIdx.x;
    const int wid  = tid >> 5;
    const int lane = tid & 31;
    const int wm   = wid & 1;
    const int wn   = wid >> 1;
    const int row0  = blockIdx.x * 128;
    const int wcol0 = blockIdx.y * col_y;

    Bhi += (size_t)blockIdx.y * w_y_off;
    Blo += (size_t)blockIdx.y * w_y_off;
    if (outF) outF += (size_t)blockIdx.y * out_y_off;

    const bool aIsF32 = (Xf != nullptr);
    const int nCh = kTot >> 5;

    float acc[4][4][4];
#pragma unroll
    for (int i = 0; i < 4; i++)
#pragma unroll
        for (int j = 0; j < 4; j++)
#pragma unroll
            for (int l = 0; l < 4; l++) acc[i][j][l] = 0.0f;

    float4 ap[4];   // fp32-A prefetch registers

#define PREFETCH_B(kc, st) do {                                                    \
        uint32_t base = sb + (uint32_t)(st) * STG;                                 \
        _Pragma("unroll")                                                          \
        for (int i = 0; i < 2; i++) {                                              \
            int u = tid + i * 256;                                                 \
            int kk = u >> 4, c16 = u & 15;                                         \
            size_t gsrc = (size_t)((kc) * 32 + kk) * ldw + wcol0 + c16 * 8;        \
            uint32_t d = b_swz(kk, c16);                                           \
            cp16(base + SB_HI + d, Bhi + gsrc);                                    \
            cp16(base + SB_LO + d, Blo + gsrc);                                    \
        }                                                                          \
    } while (0)

#define PREFETCH_A_BF(kc, st) do {                                                 \
        uint32_t base = sb + (uint32_t)(st) * STG;                                 \
        _Pragma("unroll")                                                          \
        for (int i = 0; i < 2; i++) {                                              \
            int u = tid + i * 256;                                                 \
            int r = u >> 2, c16 = u & 3;                                           \
            int row = row0 + r;                                                    \
            size_t gsrc = (size_t)row * ldx + (kc) * 32 + c16 * 8;                 \
            int bytes = (row < M) ? 16 : 0;                                        \
            uint32_t d = a_swz(r, c16);                                            \
            cp16z(base + SA_HI + d, Ahi + gsrc, bytes);                            \
            cp16z(base + SA_LO + d, Alo + gsrc, bytes);                            \
        }                                                                          \
    } while (0)

#define LDG_A(kc) do {                                                             \
        _Pragma("unroll")                                                          \
        for (int i = 0; i < 4; i++) {                                              \
            int u = tid + i * 256;                                                 \
            int r = u >> 3, c4 = u & 7;                                            \
            int row = row0 + r;                                                    \
            ap[i] = (row < M)                                                      \
                ? *(const float4*)&Xf[(size_t)row * ldx + (kc) * 32 + c4 * 4]      \
                : make_float4(0.f, 0.f, 0.f, 0.f);                                 \
        }                                                                          \
    } while (0)

#define STS_A(st) do {                                                             \
        _Pragma("unroll")                                                          \
        for (int i = 0; i < 4; i++) {                                              \
            int u = tid + i * 256;                                                 \
            int r = u >> 3, c4 = u & 7;                                            \
            __nv_bfloat162 h0 = __floats2bfloat162_rn(ap[i].x, ap[i].y);           \
            __nv_bfloat162 h1 = __floats2bfloat162_rn(ap[i].z, ap[i].w);           \
            float l0 = ap[i].x - __bfloat162float(__low2bfloat16(h0));             \
            float l1 = ap[i].y - __bfloat162float(__high2bfloat16(h0));            \
            float l2 = ap[i].z - __bfloat162float(__low2bfloat16(h1));             \
            float l3 = ap[i].w - __bfloat162float(__high2bfloat16(h1));            \
            __nv_bfloat162 g0 = __floats2bfloat162_rn(l0, l1);                     \
            __nv_bfloat162 g1 = __floats2bfloat162_rn(l2, l3);                     \
            uint32_t d = a_swz(r, c4 >> 1) + (uint32_t)((c4 & 1) << 3);            \
            *(uint2*)(smem + (st) * STG + SA_HI + d)                               \
                = make_uint2(__bfloat162_as_uint(h0), __bfloat162_as_uint(h1));    \
            *(uint2*)(smem + (st) * STG + SA_LO + d)                               \
                = make_uint2(__bfloat162_as_uint(g0), __bfloat162_as_uint(g1));    \
        }                                                                          \
    } while (0)

    // ---- prologue: prefetch chunk 0 ----
    PREFETCH_B(0, 0);
    if (!aIsF32) PREFETCH_A_BF(0, 0);
    cp_commit();
    if (aIsF32) LDG_A(0);

    // ldmatrix lane coordinates
    const int a_r  = wm * 64 + (lane & 15);
    const int a_k8 = (lane >> 4) << 3;
    const int b_k  = (((lane >> 3) & 1) << 3) + (lane & 7);
    const int b_n  = wn * 32 + ((lane >> 4) << 3);

    for (int kc = 0; kc < nCh; kc++) {
        const int s = kc & 1;
        const uint32_t base = sb + (uint32_t)s * STG;

        cp_wait0();
        if (aIsF32) STS_A(s);
        __syncthreads();

        if (kc + 1 < nCh) {
            PREFETCH_B(kc + 1, s ^ 1);
            if (!aIsF32) PREFETCH_A_BF(kc + 1, s ^ 1);
            cp_commit();
            if (aIsF32) LDG_A(kc + 1);
        } else {
            cp_commit();   // keep wait_group balanced
        }

#pragma unroll
        for (int ks = 0; ks < 2; ks++) {
            const int k0 = ks * 16;
            // B fragments
            uint32_t bh[4][2], bl[4][2];
            {
                int kk = k0 + b_k;
#pragma unroll
                for (int pair = 0; pair < 2; pair++) {
                    int n = b_n + pair * 16;
                    uint32_t addr = (uint32_t)kk * 256u
                        + (((uint32_t)(n * 2)) ^ (uint32_t)((kk & 7) << 4));
                    uint32_t r[4];
                    ldsm_x4_t(r, base + SB_HI + addr);
                    bh[2 * pair][0] = r[0]; bh[2 * pair][1] = r[1];
                    bh[2 * pair + 1][0] = r[2]; bh[2 * pair + 1][1] = r[3];
                    ldsm_x4_t(r, base + SB_LO + addr);
                    bl[2 * pair][0] = r[0]; bl[2 * pair][1] = r[1];
                    bl[2 * pair + 1][0] = r[2]; bl[2 * pair + 1][1] = r[3];
                }
            }
            // A hi fragments
            uint32_t a[4][4];
            {
                int kk = k0 + a_k8;
#pragma unroll
                for (int mf = 0; mf < 4; mf++) {
                    int r = a_r + mf * 16;
                    ldsm_x4(a[mf], base + SA_HI + a_swz(r, kk >> 3));
                }
            }
#pragma unroll
            for (int mf = 0; mf < 4; mf++)
#pragma unroll
                for (int nf = 0; nf < 4; nf++) {
                    mma16816(acc[mf][nf], a[mf], bh[nf]);
                    mma16816(acc[mf][nf], a[mf], bl[nf]);
                }
            // A lo fragments
            {
                int kk = k0 + a_k8;
#pragma unroll
                for (int mf = 0; mf < 4; mf++) {
                    int r = a_r + mf * 16;
                    ldsm_x4(a[mf], base + SA_LO + a_swz(r, kk >> 3));
                }
            }
#pragma unroll
            for (int mf = 0; mf < 4; mf++)
#pragma unroll
                for (int nf = 0; nf < 4; nf++)
                    mma16816(acc[mf][nf], a[mf], bh[nf]);
        }
        __syncthreads();
    }

    // ---- epilogue ----
    const int g = lane >> 2;
    const int t = lane & 3;
#pragma unroll
    for (int mf = 0; mf < 4; mf++) {
#pragma unroll
        for (int nf = 0; nf < 4; nf++) {
            int cl = wn * 32 + nf * 8 + 2 * t;
            float b0 = 0.f, b1 = 0.f;
            if (bias) { b0 = bias[wcol0 + cl]; b1 = bias[wcol0 + cl + 1]; }
#pragma unroll
            for (int half = 0; half < 2; half++) {
                int r = row0 + wm * 64 + mf * 16 + g + half * 8;
                if (r >= M) continue;
                float v0 = acc[mf][nf][2 * half]     + b0;
                float v1 = acc[mf][nf][2 * half + 1] + b1;
                if (doGelu) { v0 = gelu1(v0); v1 = gelu1(v1); }
                if (res) {
                    float2 rv = *(const float2*)&res[(size_t)r * 128 + cl];
                    v0 += rv.x; v1 += rv.y;
                }
                if (outF) {
                    *(float2*)&outF[(size_t)r * ldo + wcol0 + cl] = make_float2(v0, v1);
                } else {
                    __nv_bfloat162 h = __floats2bfloat162_rn(v0, v1);
                    float l0 = v0 - __bfloat162float(__low2bfloat16(h));
                    float l1 = v1 - __bfloat162float(__high2bfloat16(h));
                    __nv_bfloat162 l = __floats2bfloat162_rn(l0, l1);
                    *(__nv_bfloat162*)&outBhi[(size_t)r * 128 + cl] = h;
                    *(__nv_bfloat162*)&outBlo[(size_t)r * 128 + cl] = l;
                }
            }
        }
    }
#undef PREFETCH_B
#undef PREFETCH_A_BF
#undef LDG_A
#undef STS_A
}

// ---------------- weight splitting (once) ------------------------------------------
__global__ void split_weights_kernel(
    const float* __restrict__ Wq, const float* __restrict__ Wk,
    const float* __restrict__ Wv, const float* __restrict__ Wrel,
    const float* __restrict__ Wproj, const float* __restrict__ Wew,
    const float* __restrict__ W1, const float* __restrict__ W2,
    __nv_bfloat16* __restrict__ hi, __nv_bfloat16* __restrict__ lo)
{
    int i = blockIdx.x * blockDim.x + threadIdx.x;
    if (i >= WBF_TOTAL) return;
    float x;
    if (i < WOFF_K)           x = Wq[i];
    else if (i < WOFF_V)      x = Wk[i - WOFF_K];
    else if (i < WOFF_REL)    x = Wv[i - WOFF_V];
    else if (i < WOFF_PROJ)   x = Wrel[i - WOFF_REL];
    else if (i < WOFF_EW)     x = Wproj[i - WOFF_PROJ];
    else if (i < WOFF_W1)     x = Wew[i - WOFF_EW];
    else if (i < WOFF_W2)     x = W1[i - WOFF_W1];
    else                      x = W2[i - WOFF_W2];
    __nv_bfloat16 h = __float2bfloat16(x);
    hi[i] = h;
    lo[i] = __float2bfloat16(x - __bfloat162float(h));
}

// ---------------- generic fp32 -> bf16 hi/lo split ----------------------------------
__global__ void split_x_kernel(const float* __restrict__ x,
                               __nv_bfloat16* __restrict__ hi,
                               __nv_bfloat16* __restrict__ lo, size_t n)
{
    size_t i = (size_t)blockIdx.x * blockDim.x + threadIdx.x;
    size_t stride = (size_t)gridDim.x * blockDim.x;
    for (; i < n; i += stride) {
        float v = x[i];
        __nv_bfloat16 h = __float2bfloat16(v);
        hi[i] = h;
        lo[i] = __float2bfloat16(v - __bfloat162float(h));
    }
}

// ---------------- zero kernel --------------------------------------------------------
__global__ void zero_kernel(float* __restrict__ p, size_t n) {
    size_t i = (size_t)blockIdx.x * blockDim.x + threadIdx.x;
    size_t stride = (size_t)gridDim.x * blockDim.x;
    for (; i < n; i += stride) p[i] = 0.0f;
}

// ---------------- edge scores + softmax denominators --------------------------------
__global__ void score_kernel(
    const float* __restrict__ q, const float* __restrict__ k,
    const int* __restrict__ src, const int* __restrict__ dst,
    float* __restrict__ escore, float* __restrict__ den, int E)
{
    long idx = (long)blockIdx.x * blockDim.x + threadIdx.x;
    if (idx >= (long)E * HH) return;
    int e = (int)(idx >> 3);
    int h = (int)(idx & 7);
    int s = src[e], d = dst[e];
    const float4* qp = (const float4*)&q[(size_t)d * CC + h * 16];
    const float4* kp = (const float4*)&k[(size_t)s * CC + h * 16];
    float acc = 0.f;
#pragma unroll
    for (int i = 0; i < 4; i++) {
        float4 a = qp[i], b = kp[i];
        acc += a.x * b.x + a.y * b.y + a.z * b.z + a.w * b.w;
    }
    acc *= 0.25f;
    acc = fminf(fmaxf(acc, -10.0f), 10.0f);
    float ex = expf(acc);
    escore[idx] = ex;
    atomicAdd(&den[(size_t)d * HH + h], ex);
}

// ---------------- edge aggregation ---------------------------------------------------
__global__ void agg_kernel(
    const float* __restrict__ vt, const float* __restrict__ efeat,
    const float* __restrict__ escore, const float* __restrict__ den,
    const int* __restrict__ src, const int* __restrict__ dst,
    const int* __restrict__ etype,
    float* __restrict__ wv, int E, int Nn)
{
    int e = (int)(((long)blockIdx.x * blockDim.x + threadIdx.x) >> 5);
    if (e >= E) return;
    int lane = threadIdx.x & 31;
    int s = src[e], d = dst[e], t = etype[e];
    int h = lane >> 2;
    float alpha = escore[(size_t)e * HH + h] / den[(size_t)d * HH + h];
    float4 vv = *(const float4*)&vt[((size_t)t * Nn + s) * CC + lane * 4];
    float4 ef = *(const float4*)&efeat[(size_t)e * CC + lane * 4];
    float m0 = (vv.x - ef.x) * alpha;
    float m1 = (vv.y - ef.y) * alpha;
    float m2 = (vv.z - ef.z) * alpha;
    float m3 = (vv.w - ef.w) * alpha;
    float* p = &wv[(size_t)d * CC + lane * 4];
    asm volatile("red.global.add.v4.f32 [%0], {%1, %2, %3, %4};"
                 :: "l"(p), "f"(m0), "f"(m1), "f"(m2), "f"(m3) : "memory");
}

// ---------------- layernorm, emits bf16 hi/lo ----------------------------------------
__global__ void ln_kernel(
    const float* __restrict__ x, const float* __restrict__ g,
    const float* __restrict__ b,
    __nv_bfloat16* __restrict__ ohi, __nv_bfloat16* __restrict__ olo, int M)
{
    int row = (int)(((long)blockIdx.x * blockDim.x + threadIdx.x) >> 5);
    if (row >= M) return;
    int lane = threadIdx.x & 31;
    float4 v = *(const float4*)&x[(size_t)row * CC + lane * 4];
    float s = v.x + v.y + v.z + v.w;
#pragma unroll
    for (int o = 16; o > 0; o >>= 1) s += __shfl_xor_sync(0xffffffffu, s, o);
    float mu = s * (1.0f / 128.0f);
    float d0 = v.x - mu, d1 = v.y - mu, d2 = v.z - mu, d3 = v.w - mu;
    float ss = d0 * d0 + d1 * d1 + d2 * d2 + d3 * d3;
#pragma unroll
    for (int o = 16; o > 0; o >>= 1) ss += __shfl_xor_sync(0xffffffffu, ss, o);
    float inv = rsqrtf(ss * (1.0f / 128.0f) + 1e-5f);
    float4 gg = *(const float4*)&g[lane * 4];
    float4 bb = *(const float4*)&b[lane * 4];
    float o0 = d0 * inv * gg.x + bb.x;
    float o1 = d1 * inv * gg.y + bb.y;
    float o2 = d2 * inv * gg.z + bb.z;
    float o3 = d3 * inv * gg.w + bb.w;
    __nv_bfloat162 h0 = __floats2bfloat162_rn(o0, o1);
    __nv_bfloat162 h1 = __floats2bfloat162_rn(o2, o3);
    __nv_bfloat162 l0 = __floats2bfloat162_rn(
        o0 - __bfloat162float(__low2bfloat16(h0)),
        o1 - __bfloat162float(__high2bfloat16(h0)));
    __nv_bfloat162 l1 = __floats2bfloat162_rn(
        o2 - __bfloat162float(__low2bfloat16(h1)),
        o3 - __bfloat162float(__high2bfloat16(h1)));
    size_t o = (size_t)row * CC + lane * 4;
    *(__nv_bfloat162*)&ohi[o]     = h0;
    *(__nv_bfloat162*)&ohi[o + 2] = h1;
    *(__nv_bfloat162*)&olo[o]     = l0;
    *(__nv_bfloat162*)&olo[o + 2] = l1;
}

// ---------------- host side -----------------------------------------------------------
struct GemmArgs {
    const float* Xf;
    const __nv_bfloat16 *Ahi, *Alo;
    int ldx, kTot;
    size_t wOff; int ldw; size_t w_y_off; int col_y;
    const float* bias; const float* res;
    float* outF; int ldo; size_t out_y_off;
    __nv_bfloat16 *outBhi, *outBlo;
    int M, nY, doGelu;
};

static __nv_bfloat16 *h_wbf_hi, *h_wbf_lo;

static inline void launch_gemm(const GemmArgs& a)
{
    dim3 grid((a.M + 127) / 128, a.nY);
    gemm_bf16_kernel<<<grid, 256, SM_TOTAL>>>(
        a.Xf, a.Ahi, a.Alo, a.ldx, a.kTot,
        h_wbf_hi + a.wOff, h_wbf_lo + a.wOff,
        a.ldw, a.w_y_off, a.col_y,
        a.bias, a.res, a.outF, a.ldo, a.out_y_off,
        a.outBhi, a.outBlo, a.M, a.doGelu);
}

extern "C" void kernel_launch(void* const* d_in, const int* in_sizes, int n_in,
                              void* d_out, int out_size)
{
    const float* feat  = (const float*)d_in[0];
    const float* efeat = (const float*)d_in[1];
    const int*   src   = (const int*)d_in[2];
    const int*   dst   = (const int*)d_in[3];
    const int*   etype = (const int*)d_in[4];

    int base = 5;
    if (in_sizes[5] == 1) base = 6;

    const float* Wq    = (const float*)d_in[base + 0];
    const float* bq    = (const float*)d_in[base + 1];
    const float* Wk    = (const float*)d_in[base + 2];
    const float* bk    = (const float*)d_in[base + 3];
    const float* Wv    = (const float*)d_in[base + 4];
    const float* bv    = (const float*)d_in[base + 5];
    const float* W_rel = (const float*)d_in[base + 6];
    const float* Wproj = (const float*)d_in[base + 7];
    const float* bproj = (const float*)d_in[base + 8];
    const float* WeW   = (const float*)d_in[base + 9];
    const float* beW   = (const float*)d_in[base + 10];
    const float* ln_g  = (const float*)d_in[base + 11];
    const float* ln_b  = (const float*)d_in[base + 12];
    const float* W1    = (const float*)d_in[base + 13];
    const float* b1    = (const float*)d_in[base + 14];
    const float* W2    = (const float*)d_in[base + 15];
    const float* b2    = (const float*)d_in[base + 16];

    const int N = in_sizes[0] / CC;
    const int E = in_sizes[1] / CC;

    float *qk, *vt, *esc, *den, *wv, *feat1, *hmid;
    __nv_bfloat16 *vhi, *vlo, *fhi, *flo, *hnhi, *hnlo;
    cudaGetSymbolAddress((void**)&qk,    g_qk);
    cudaGetSymbolAddress((void**)&vt,    g_vt);
    cudaGetSymbolAddress((void**)&esc,   g_escore);
    cudaGetSymbolAddress((void**)&den,   g_den);
    cudaGetSymbolAddress((void**)&wv,    g_wv);
    cudaGetSymbolAddress((void**)&feat1, g_feat1);
    cudaGetSymbolAddress((void**)&hmid,  g_hmid);
    cudaGetSymbolAddress((void**)&vhi,   g_vhi);
    cudaGetSymbolAddress((void**)&vlo,   g_vlo);
    cudaGetSymbolAddress((void**)&fhi,   g_feathi);
    cudaGetSymbolAddress((void**)&flo,   g_featlo);
    cudaGetSymbolAddress((void**)&hnhi,  g_hnhi);
    cudaGetSymbolAddress((void**)&hnlo,  g_hnlo);
    cudaGetSymbolAddress((void**)&h_wbf_hi, g_wbf_hi);
    cudaGetSymbolAddress((void**)&h_wbf_lo, g_wbf_lo);

    cudaFuncSetAttribute(gemm_bf16_kernel,
                         cudaFuncAttributeMaxDynamicSharedMemorySize, SM_TOTAL);

    float* out_feat  = (float*)d_out;
    float* out_efeat = (float*)d_out + (size_t)N * CC;
    float* q = qk;
    float* k = qk + (size_t)N * CC;

    // 0) one-time prep: weight split, feat split, zero accumulators
    split_weights_kernel<<<(WBF_TOTAL + 255) / 256, 256>>>(
        Wq, Wk, Wv, W_rel, Wproj, WeW, W1, W2, h_wbf_hi, h_wbf_lo);
    split_x_kernel<<<512, 256>>>(feat, fhi, flo, (size_t)N * CC);
    zero_kernel<<<512, 256>>>(den, (size_t)N * HH);
    zero_kernel<<<512, 256>>>(wv,  (size_t)N * CC);

    GemmArgs a{};
    a.ldx = CC; a.kTot = CC; a.ldw = CC; a.w_y_off = 0; a.col_y = 0;
    a.ldo = CC; a.out_y_off = 0; a.M = N; a.nY = 1; a.doGelu = 0;

    // 1) q, k projections (bf16 A = feat)
    a.Ahi = fhi; a.Alo = flo;
    a.wOff = WOFF_Q; a.bias = bq; a.outF = q;   launch_gemm(a);
    a.wOff = WOFF_K; a.bias = bk; a.outF = k;   launch_gemm(a);
    // v projection -> bf16 hi/lo output
    a.wOff = WOFF_V; a.bias = bv; a.outF = nullptr;
    a.outBhi = vhi; a.outBlo = vlo;             launch_gemm(a);
    a.outBhi = nullptr; a.outBlo = nullptr;

    // 2) vt[t] = v @ W_rel[t], single launch grid.y = 8
    a.Ahi = vhi; a.Alo = vlo;
    a.wOff = WOFF_REL; a.w_y_off = 16384; a.bias = nullptr;
    a.outF = vt; a.out_y_off = (size_t)N * CC; a.nY = TT;  launch_gemm(a);
    a.w_y_off = 0; a.out_y_off = 0; a.nY = 1;

    // 3) edge scores + denominators
    {
        long total = (long)E * HH;
        score_kernel<<<(int)((total + 255) / 256), 256>>>(q, k, src, dst, esc, den, E);
    }
    // 4) edge aggregation
    {
        long total = (long)E * 32;
        agg_kernel<<<(int)((total + 255) / 256), 256>>>(vt, efeat, esc, den,
                                                        src, dst, etype, wv, E, N);
    }

    // 5) feat1 = feat + wv @ Wproj + bproj   (fp32 A inline)
    a.Ahi = nullptr; a.Alo = nullptr; a.Xf = wv;
    a.wOff = WOFF_PROJ; a.bias = bproj; a.res = feat; a.outF = feat1;
    launch_gemm(a);
    a.res = nullptr;

    // 6) hn = layernorm(feat1) -> bf16 hi/lo
    {
        long total = (long)N * 32;
        ln_kernel<<<(int)((total + 255) / 256), 256>>>(feat1, ln_g, ln_b, hnhi, hnlo, N);
    }

    // 7) hmid = gelu(hn @ W1 + b1), grid.y = 4 column chunks
    a.Xf = nullptr; a.Ahi = hnhi; a.Alo = hnlo;
    a.wOff = WOFF_W1; a.ldw = 4 * CC; a.col_y = 128; a.bias = b1;
    a.outF = hmid; a.ldo = 4 * CC; a.nY = 4; a.doGelu = 1;
    launch_gemm(a);
    a.col_y = 0; a.nY = 1; a.doGelu = 0;

    // 8) feat_out = feat1 + hmid @ W2 + b2   (fp32 A, K = 512)
    a.Ahi = nullptr; a.Alo = nullptr; a.Xf = hmid;
    a.ldx = 4 * CC; a.kTot = 4 * CC; a.wOff = WOFF_W2; a.ldw = CC;
    a.bias = b2; a.res = feat1; a.outF = out_feat; a.ldo = CC;
    launch_gemm(a);
    a.res = nullptr; a.ldx = CC; a.kTot = CC;

    // 9) efeat_out = efeat @ WeW + beW   (fp32 A, E rows)
    a.Xf = efeat; a.wOff = WOFF_EW; a.bias = beW;
    a.outF = out_efeat; a.M = E;
    launch_gemm(a);
}

// round 6
// speedup vs baseline: 2.7126x; 1.1404x over previous
#include <cuda_runtime.h>
#include <cuda_fp16.h>
#include <math.h>
#include <stdint.h>

// Problem constants
#define NN 50000
#define EE 800000
#define CC 128
#define HH 8
#define TT 8

// ---------------- scratch (device globals) -------------------------------------
__device__ float g_qk[(size_t)2 * NN * CC];          // q then k
__device__ __half g_vhi[(size_t)NN * CC];
__device__ __half g_vlo[(size_t)NN * CC];
__device__ __half g_feathi[(size_t)NN * CC];
__device__ __half g_featlo[(size_t)NN * CC];
__device__ __half g_hnhi[(size_t)NN * CC];
__device__ __half g_hnlo[(size_t)NN * CC];
__device__ float g_vt[(size_t)TT * NN * CC];
__device__ float g_escore[(size_t)EE * HH];
__device__ float g_den[(size_t)NN * HH];
__device__ float g_wv[(size_t)NN * CC];
__device__ float g_feat1[(size_t)NN * CC];
__device__ float g_hmid[(size_t)NN * 4 * CC];
__device__ float g_bias_qk[2 * CC];

// fp16 weights (single precision-level; A side carries the exact split)
#define WOFF_Q    0
#define WOFF_K    16384
#define WOFF_V    32768
#define WOFF_REL  49152
#define WOFF_PROJ 180224
#define WOFF_EW   196608
#define WOFF_W1   212992
#define WOFF_W2   278528
#define WBF_TOTAL 344064
__device__ __half g_wh[WBF_TOTAL];

// ---------------- helpers (all defined BEFORE use) ---------------------------------
__device__ __forceinline__ uint32_t half2_u(__half2 v) {
    return *reinterpret_cast<uint32_t*>(&v);
}
__device__ __forceinline__ uint32_t smem_u32(const void* p) {
    uint32_t addr;
    asm("{ .reg .u64 t; cvta.to.shared.u64 t, %1; cvt.u32.u64 %0, t; }"
        : "=r"(addr) : "l"(p));
    return addr;
}
__device__ __forceinline__ void ldsm_x4(uint32_t* r, uint32_t addr) {
    asm volatile("ldmatrix.sync.aligned.m8n8.x4.shared.b16 {%0,%1,%2,%3}, [%4];"
                 : "=r"(r[0]), "=r"(r[1]), "=r"(r[2]), "=r"(r[3]) : "r"(addr));
}
__device__ __forceinline__ void ldsm_x4_t(uint32_t* r, uint32_t addr) {
    asm volatile("ldmatrix.sync.aligned.m8n8.x4.trans.shared.b16 {%0,%1,%2,%3}, [%4];"
                 : "=r"(r[0]), "=r"(r[1]), "=r"(r[2]), "=r"(r[3]) : "r"(addr));
}
__device__ __forceinline__ void mma16816(float* c, const uint32_t* a, const uint32_t* b) {
    asm volatile(
        "mma.sync.aligned.m16n8k16.row.col.f32.f16.f16.f32 "
        "{%0,%1,%2,%3}, {%4,%5,%6,%7}, {%8,%9}, {%0,%1,%2,%3};"
        : "+f"(c[0]), "+f"(c[1]), "+f"(c[2]), "+f"(c[3])
        : "r"(a[0]), "r"(a[1]), "r"(a[2]), "r"(a[3]), "r"(b[0]), "r"(b[1]));
}
__device__ __forceinline__ void cp16(uint32_t dst, const void* src) {
    asm volatile("cp.async.cg.shared.global [%0], [%1], 16;"
                 :: "r"(dst), "l"(src) : "memory");
}
__device__ __forceinline__ void cp16z(uint32_t dst, const void* src, int bytes) {
    asm volatile("cp.async.cg.shared.global [%0], [%1], 16, %2;"
                 :: "r"(dst), "l"(src), "r"(bytes) : "memory");
}
__device__ __forceinline__ void cp_commit() {
    asm volatile("cp.async.commit_group;" ::: "memory");
}
__device__ __forceinline__ void cp_wait0() {
    asm volatile("cp.async.wait_group 0;" ::: "memory");
}

// smem tile swizzles
// A tile: 128 rows x 32 k fp16, 64B rows
__device__ __forceinline__ uint32_t a_swz(int r, int c16) {
    return (uint32_t)r * 64u + (uint32_t)((c16 ^ ((r >> 1) & 3)) << 4);
}
// B tile: 32 k-rows x 128 n fp16, 256B rows
__device__ __forceinline__ uint32_t b_swz(int k, int c16) {
    return (uint32_t)k * 256u + (uint32_t)((c16 ^ (k & 7)) << 4);
}
__device__ __forceinline__ float gelu1(float v) {
    return 0.5f * v * (1.0f + erff(v * 0.70710678118654752f));
}

// ---------------- pipelined fp16 tensor-core GEMM ---------------------------------
// CTA tile 128x128, K-chunk 32, double-buffered cp.async stages.
// 2-pass exact-A: D = Ah@Bh + Al@Bh  (A = Ah+Al fp16 split, B single fp16).
// stage layout (24KB): Ahi @0, Alo @8K, B @16K;  stage1 @24K.
#define STG 24576
#define SA_HI 0
#define SA_LO 8192
#define SB_HI 16384
#define SM_TOTAL 49152

__global__ void __launch_bounds__(256, 2) gemm_fp16_kernel(
    const float* __restrict__ Xf,                 // fp32 A (or null)
    const __half* __restrict__ Ahi,               // fp16 A (or null)
    const __half* __restrict__ Alo,
    int ldx, int kTot,
    const __half* __restrict__ Bh,                // fp16 weights
    int ldw, size_t w_y_off, int col_y,
    const float* __restrict__ bias,               // nullable
    int bias_y_off,
    const float* __restrict__ res,                // nullable, ld=128
    float* __restrict__ outF, int ldo, size_t out_y_off,
    __half* __restrict__ outHhi,                  // fp16 hi/lo out mode (v)
    __half* __restrict__ outHlo,
    int M, int doGelu)
{
    extern __shared__ char smem[];
    const uint32_t sb = smem_u32(smem);
    const int tid  = threadIdx.x;
    const int wid  = tid >> 5;
    const int lane = tid & 31;
    const int wm   = wid & 1;
    const int wn   = wid >> 1;
    const int row0  = blockIdx.x * 128;
    const int wcol0 = blockIdx.y * col_y;

    Bh += (size_t)blockIdx.y * w_y_off;
    if (outF) outF += (size_t)blockIdx.y * out_y_off;
    if (bias) bias += (size_t)blockIdx.y * bias_y_off;

    const bool aIsF32 = (Xf != nullptr);
    const int nCh = kTot >> 5;

    float acc[4][4][4];
#pragma unroll
    for (int i = 0; i < 4; i++)
#pragma unroll
        for (int j = 0; j < 4; j++)
#pragma unroll
            for (int l = 0; l < 4; l++) acc[i][j][l] = 0.0f;

    float4 ap[4];   // fp32-A prefetch registers

#define PREFETCH_B(kc, st) do {                                                    \
        uint32_t base = sb + (uint32_t)(st) * STG;                                 \
        _Pragma("unroll")                                                          \
        for (int i = 0; i < 2; i++) {                                              \
            int u = tid + i * 256;                                                 \
            int kk = u >> 4, c16 = u & 15;                                         \
            size_t gsrc = (size_t)((kc) * 32 + kk) * ldw + wcol0 + c16 * 8;        \
            cp16(base + SB_HI + b_swz(kk, c16), Bh + gsrc);                        \
        }                                                                          \
    } while (0)

#define PREFETCH_A_HF(kc, st) do {                                                 \
        uint32_t base = sb + (uint32_t)(st) * STG;                                 \
        _Pragma("unroll")                                                          \
        for (int i = 0; i < 2; i++) {                                              \
            int u = tid + i * 256;                                                 \
            int r = u >> 2, c16 = u & 3;                                           \
            int row = row0 + r;                                                    \
            size_t gsrc = (size_t)row * ldx + (kc) * 32 + c16 * 8;                 \
            int bytes = (row < M) ? 16 : 0;                                        \
            uint32_t d = a_swz(r, c16);                                            \
            cp16z(base + SA_HI + d, Ahi + gsrc, bytes);                            \
            cp16z(base + SA_LO + d, Alo + gsrc, bytes);                            \
        }                                                                          \
    } while (0)

#define LDG_A(kc) do {                                                             \
        _Pragma("unroll")                                                          \
        for (int i = 0; i < 4; i++) {                                              \
            int u = tid + i * 256;                                                 \
            int r = u >> 3, c4 = u & 7;                                            \
            int row = row0 + r;                                                    \
            ap[i] = (row < M)                                                      \
                ? *(const float4*)&Xf[(size_t)row * ldx + (kc) * 32 + c4 * 4]      \
                : make_float4(0.f, 0.f, 0.f, 0.f);                                 \
        }                                                                          \
    } while (0)

#define STS_A(st) do {                                                             \
        _Pragma("unroll")                                                          \
        for (int i = 0; i < 4; i++) {                                              \
            int u = tid + i * 256;                                                 \
            int r = u >> 3, c4 = u & 7;                                            \
            __half2 h0 = __floats2half2_rn(ap[i].x, ap[i].y);                      \
            __half2 h1 = __floats2half2_rn(ap[i].z, ap[i].w);                      \
            float l0 = ap[i].x - __low2float(h0);                                  \
            float l1 = ap[i].y - __high2float(h0);                                 \
            float l2 = ap[i].z - __low2float(h1);                                  \
            float l3 = ap[i].w - __high2float(h1);                                 \
            __half2 g0 = __floats2half2_rn(l0, l1);                                \
            __half2 g1 = __floats2half2_rn(l2, l3);                                \
            uint32_t d = a_swz(r, c4 >> 1) + (uint32_t)((c4 & 1) << 3);            \
            *(uint2*)(smem + (st) * STG + SA_HI + d)                               \
                = make_uint2(half2_u(h0), half2_u(h1));                            \
            *(uint2*)(smem + (st) * STG + SA_LO + d)                               \
                = make_uint2(half2_u(g0), half2_u(g1));                            \
        }                                                                          \
    } while (0)

    // ---- prologue ----
    PREFETCH_B(0, 0);
    if (!aIsF32) PREFETCH_A_HF(0, 0);
    cp_commit();
    if (aIsF32) LDG_A(0);

    // ldmatrix lane coordinates
    const int a_r  = wm * 64 + (lane & 15);
    const int a_k8 = (lane >> 4) << 3;
    const int b_k  = (((lane >> 3) & 1) << 3) + (lane & 7);
    const int b_n  = wn * 32 + ((lane >> 4) << 3);

    for (int kc = 0; kc < nCh; kc++) {
        const int s = kc & 1;
        const uint32_t base = sb + (uint32_t)s * STG;

        cp_wait0();
        if (aIsF32) STS_A(s);
        __syncthreads();

        if (kc + 1 < nCh) {
            PREFETCH_B(kc + 1, s ^ 1);
            if (!aIsF32) PREFETCH_A_HF(kc + 1, s ^ 1);
            cp_commit();
            if (aIsF32) LDG_A(kc + 1);
        } else {
            cp_commit();
        }

#pragma unroll
        for (int ks = 0; ks < 2; ks++) {
            const int k0 = ks * 16;
            // B fragments (single precision level)
            uint32_t bh[4][2];
            {
                int kk = k0 + b_k;
#pragma unroll
                for (int pair = 0; pair < 2; pair++) {
                    int n = b_n + pair * 16;
                    uint32_t addr = (uint32_t)kk * 256u
                        + (((uint32_t)(n * 2)) ^ (uint32_t)((kk & 7) << 4));
                    uint32_t r[4];
                    ldsm_x4_t(r, base + SB_HI + addr);
                    bh[2 * pair][0] = r[0]; bh[2 * pair][1] = r[1];
                    bh[2 * pair + 1][0] = r[2]; bh[2 * pair + 1][1] = r[3];
                }
            }
            // A hi pass
            uint32_t a[4][4];
            {
                int kk = k0 + a_k8;
#pragma unroll
                for (int mf = 0; mf < 4; mf++)
                    ldsm_x4(a[mf], base + SA_HI + a_swz(a_r + mf * 16, kk >> 3));
            }
#pragma unroll
            for (int mf = 0; mf < 4; mf++)
#pragma unroll
                for (int nf = 0; nf < 4; nf++)
                    mma16816(acc[mf][nf], a[mf], bh[nf]);
            // A lo pass
            {
                int kk = k0 + a_k8;
#pragma unroll
                for (int mf = 0; mf < 4; mf++)
                    ldsm_x4(a[mf], base + SA_LO + a_swz(a_r + mf * 16, kk >> 3));
            }
#pragma unroll
            for (int mf = 0; mf < 4; mf++)
#pragma unroll
                for (int nf = 0; nf < 4; nf++)
                    mma16816(acc[mf][nf], a[mf], bh[nf]);
        }
        __syncthreads();
    }

    // ---- epilogue ----
    const int g = lane >> 2;
    const int t = lane & 3;
#pragma unroll
    for (int mf = 0; mf < 4; mf++) {
#pragma unroll
        for (int nf = 0; nf < 4; nf++) {
            int cl = wn * 32 + nf * 8 + 2 * t;
            float b0 = 0.f, b1 = 0.f;
            if (bias) { b0 = bias[wcol0 + cl]; b1 = bias[wcol0 + cl + 1]; }
#pragma unroll
            for (int half = 0; half < 2; half++) {
                int r = row0 + wm * 64 + mf * 16 + g + half * 8;
                if (r >= M) continue;
                float v0 = acc[mf][nf][2 * half]     + b0;
                float v1 = acc[mf][nf][2 * half + 1] + b1;
                if (doGelu) { v0 = gelu1(v0); v1 = gelu1(v1); }
                if (res) {
                    float2 rv = *(const float2*)&res[(size_t)r * 128 + cl];
                    v0 += rv.x; v1 += rv.y;
                }
                if (outF) {
                    *(float2*)&outF[(size_t)r * ldo + wcol0 + cl] = make_float2(v0, v1);
                } else {
                    __half2 h = __floats2half2_rn(v0, v1);
                    float l0 = v0 - __low2float(h);
                    float l1 = v1 - __high2float(h);
                    __half2 l = __floats2half2_rn(l0, l1);
                    *(__half2*)&outHhi[(size_t)r * 128 + cl] = h;
                    *(__half2*)&outHlo[(size_t)r * 128 + cl] = l;
                }
            }
        }
    }
#undef PREFETCH_B
#undef PREFETCH_A_HF
#undef LDG_A
#undef STS_A
}

// ---------------- weight conversion (once) -----------------------------------------
__global__ void conv_weights_kernel(
    const float* __restrict__ Wq, const float* __restrict__ Wk,
    const float* __restrict__ Wv, const float* __restrict__ Wrel,
    const float* __restrict__ Wproj, const float* __restrict__ Wew,
    const float* __restrict__ W1, const float* __restrict__ W2,
    const float* __restrict__ bq, const float* __restrict__ bk,
    __half* __restrict__ wh, float* __restrict__ bias_qk)
{
    int i = blockIdx.x * blockDim.x + threadIdx.x;
    if (i < 2 * CC) bias_qk[i] = (i < CC) ? bq[i] : bk[i - CC];
    if (i >= WBF_TOTAL) return;
    float x;
    if (i < WOFF_K)           x = Wq[i];
    else if (i < WOFF_V)      x = Wk[i - WOFF_K];
    else if (i < WOFF_REL)    x = Wv[i - WOFF_V];
    else if (i < WOFF_PROJ)   x = Wrel[i - WOFF_REL];
    else if (i < WOFF_EW)     x = Wproj[i - WOFF_PROJ];
    else if (i < WOFF_W1)     x = Wew[i - WOFF_EW];
    else if (i < WOFF_W2)     x = W1[i - WOFF_W1];
    else                      x = W2[i - WOFF_W2];
    wh[i] = __float2half_rn(x);
}

// ---------------- fp32 -> fp16 hi/lo split + zero accumulators ----------------------
__global__ void prep_kernel(const float* __restrict__ x,
                            __half* __restrict__ hi, __half* __restrict__ lo,
                            size_t n,
                            float* __restrict__ z1, size_t n1,
                            float* __restrict__ z2, size_t n2)
{
    size_t i = (size_t)blockIdx.x * blockDim.x + threadIdx.x;
    size_t stride = (size_t)gridDim.x * blockDim.x;
    for (size_t j = i; j < n; j += stride) {
        float v = x[j];
        __half h = __float2half_rn(v);
        hi[j] = h;
        lo[j] = __float2half_rn(v - __half2float(h));
    }
    for (size_t j = i; j < n1; j += stride) z1[j] = 0.0f;
    for (size_t j = i; j < n2; j += stride) z2[j] = 0.0f;
}

// ---------------- edge scores + softmax denominators --------------------------------
__global__ void score_kernel(
    const float* __restrict__ q, const float* __restrict__ k,
    const int* __restrict__ src, const int* __restrict__ dst,
    float* __restrict__ escore, float* __restrict__ den, int E)
{
    long idx = (long)blockIdx.x * blockDim.x + threadIdx.x;
    if (idx >= (long)E * HH) return;
    int e = (int)(idx >> 3);
    int h = (int)(idx & 7);
    int s = src[e], d = dst[e];
    const float4* qp = (const float4*)&q[(size_t)d * CC + h * 16];
    const float4* kp = (const float4*)&k[(size_t)s * CC + h * 16];
    float acc = 0.f;
#pragma unroll
    for (int i = 0; i < 4; i++) {
        float4 a = qp[i], b = kp[i];
        acc += a.x * b.x + a.y * b.y + a.z * b.z + a.w * b.w;
    }
    acc *= 0.25f;
    acc = fminf(fmaxf(acc, -10.0f), 10.0f);
    float ex = expf(acc);
    escore[idx] = ex;
    atomicAdd(&den[(size_t)d * HH + h], ex);
}

// ---------------- edge aggregation ---------------------------------------------------
__global__ void agg_kernel(
    const float* __restrict__ vt, const float* __restrict__ efeat,
    const float* __restrict__ escore, const float* __restrict__ den,
    const int* __restrict__ src, const int* __restrict__ dst,
    const int* __restrict__ etype,
    float* __restrict__ wv, int E, int Nn)
{
    int e = (int)(((long)blockIdx.x * blockDim.x + threadIdx.x) >> 5);
    if (e >= E) return;
    int lane = threadIdx.x & 31;
    int s = src[e], d = dst[e], t = etype[e];
    int h = lane >> 2;
    float alpha = escore[(size_t)e * HH + h] / den[(size_t)d * HH + h];
    float4 vv = *(const float4*)&vt[((size_t)t * Nn + s) * CC + lane * 4];
    float4 ef = *(const float4*)&efeat[(size_t)e * CC + lane * 4];
    float m0 = (vv.x - ef.x) * alpha;
    float m1 = (vv.y - ef.y) * alpha;
    float m2 = (vv.z - ef.z) * alpha;
    float m3 = (vv.w - ef.w) * alpha;
    float* p = &wv[(size_t)d * CC + lane * 4];
    asm volatile("red.global.add.v4.f32 [%0], {%1, %2, %3, %4};"
                 :: "l"(p), "f"(m0), "f"(m1), "f"(m2), "f"(m3) : "memory");
}

// ---------------- layernorm, emits fp16 hi/lo ----------------------------------------
__global__ void ln_kernel(
    const float* __restrict__ x, const float* __restrict__ g,
    const float* __restrict__ b,
    __half* __restrict__ ohi, __half* __restrict__ olo, int M)
{
    int row = (int)(((long)blockIdx.x * blockDim.x + threadIdx.x) >> 5);
    if (row >= M) return;
    int lane = threadIdx.x & 31;
    float4 v = *(const float4*)&x[(size_t)row * CC + lane * 4];
    float s = v.x + v.y + v.z + v.w;
#pragma unroll
    for (int o = 16; o > 0; o >>= 1) s += __shfl_xor_sync(0xffffffffu, s, o);
    float mu = s * (1.0f / 128.0f);
    float d0 = v.x - mu, d1 = v.y - mu, d2 = v.z - mu, d3 = v.w - mu;
    float ss = d0 * d0 + d1 * d1 + d2 * d2 + d3 * d3;
#pragma unroll
    for (int o = 16; o > 0; o >>= 1) ss += __shfl_xor_sync(0xffffffffu, ss, o);
    float inv = rsqrtf(ss * (1.0f / 128.0f) + 1e-5f);
    float4 gg = *(const float4*)&g[lane * 4];
    float4 bb = *(const float4*)&b[lane * 4];
    float o0 = d0 * inv * gg.x + bb.x;
    float o1 = d1 * inv * gg.y + bb.y;
    float o2 = d2 * inv * gg.z + bb.z;
    float o3 = d3 * inv * gg.w + bb.w;
    __half2 h0 = __floats2half2_rn(o0, o1);
    __half2 h1 = __floats2half2_rn(o2, o3);
    __half2 l0 = __floats2half2_rn(o0 - __low2float(h0), o1 - __high2float(h0));
    __half2 l1 = __floats2half2_rn(o2 - __low2float(h1), o3 - __high2float(h1));
    size_t o = (size_t)row * CC + lane * 4;
    *(__half2*)&ohi[o]     = h0;
    *(__half2*)&ohi[o + 2] = h1;
    *(__half2*)&olo[o]     = l0;
    *(__half2*)&olo[o + 2] = l1;
}

// ---------------- host side -----------------------------------------------------------
struct GemmArgs {
    const float* Xf;
    const __half *Ahi, *Alo;
    int ldx, kTot;
    size_t wOff; int ldw; size_t w_y_off; int col_y;
    const float* bias; int bias_y_off; const float* res;
    float* outF; int ldo; size_t out_y_off;
    __half *outHhi, *outHlo;
    int M, nY, doGelu;
};

static __half* h_wh;

static inline void launch_gemm(const GemmArgs& a)
{
    dim3 grid((a.M + 127) / 128, a.nY);
    gemm_fp16_kernel<<<grid, 256, SM_TOTAL>>>(
        a.Xf, a.Ahi, a.Alo, a.ldx, a.kTot,
        h_wh + a.wOff, a.ldw, a.w_y_off, a.col_y,
        a.bias, a.bias_y_off, a.res, a.outF, a.ldo, a.out_y_off,
        a.outHhi, a.outHlo, a.M, a.doGelu);
}

extern "C" void kernel_launch(void* const* d_in, const int* in_sizes, int n_in,
                              void* d_out, int out_size)
{
    const float* feat  = (const float*)d_in[0];
    const float* efeat = (const float*)d_in[1];
    const int*   src   = (const int*)d_in[2];
    const int*   dst   = (const int*)d_in[3];
    const int*   etype = (const int*)d_in[4];

    int base = 5;
    if (in_sizes[5] == 1) base = 6;

    const float* Wq    = (const float*)d_in[base + 0];
    const float* bq    = (const float*)d_in[base + 1];
    const float* Wk    = (const float*)d_in[base + 2];
    const float* bk    = (const float*)d_in[base + 3];
    const float* Wv    = (const float*)d_in[base + 4];
    const float* bv    = (const float*)d_in[base + 5];
    const float* W_rel = (const float*)d_in[base + 6];
    const float* Wproj = (const float*)d_in[base + 7];
    const float* bproj = (const float*)d_in[base + 8];
    const float* WeW   = (const float*)d_in[base + 9];
    const float* beW   = (const float*)d_in[base + 10];
    const float* ln_g  = (const float*)d_in[base + 11];
    const float* ln_b  = (const float*)d_in[base + 12];
    const float* W1    = (const float*)d_in[base + 13];
    const float* b1    = (const float*)d_in[base + 14];
    const float* W2    = (const float*)d_in[base + 15];
    const float* b2    = (const float*)d_in[base + 16];

    const int N = in_sizes[0] / CC;
    const int E = in_sizes[1] / CC;

    float *qk, *vt, *esc, *den, *wv, *feat1, *hmid, *bias_qk;
    __half *vhi, *vlo, *fhi, *flo, *hnhi, *hnlo;
    cudaGetSymbolAddress((void**)&qk,    g_qk);
    cudaGetSymbolAddress((void**)&vt,    g_vt);
    cudaGetSymbolAddress((void**)&esc,   g_escore);
    cudaGetSymbolAddress((void**)&den,   g_den);
    cudaGetSymbolAddress((void**)&wv,    g_wv);
    cudaGetSymbolAddress((void**)&feat1, g_feat1);
    cudaGetSymbolAddress((void**)&hmid,  g_hmid);
    cudaGetSymbolAddress((void**)&bias_qk, g_bias_qk);
    cudaGetSymbolAddress((void**)&vhi,   g_vhi);
    cudaGetSymbolAddress((void**)&vlo,   g_vlo);
    cudaGetSymbolAddress((void**)&fhi,   g_feathi);
    cudaGetSymbolAddress((void**)&flo,   g_featlo);
    cudaGetSymbolAddress((void**)&hnhi,  g_hnhi);
    cudaGetSymbolAddress((void**)&hnlo,  g_hnlo);
    cudaGetSymbolAddress((void**)&h_wh,  g_wh);

    cudaFuncSetAttribute(gemm_fp16_kernel,
                         cudaFuncAttributeMaxDynamicSharedMemorySize, SM_TOTAL);

    float* out_feat  = (float*)d_out;
    float* out_efeat = (float*)d_out + (size_t)N * CC;
    float* q = qk;
    float* k = qk + (size_t)N * CC;

    // 0) one-time prep
    conv_weights_kernel<<<(WBF_TOTAL + 255) / 256, 256>>>(
        Wq, Wk, Wv, W_rel, Wproj, WeW, W1, W2, bq, bk, h_wh, bias_qk);
    prep_kernel<<<1024, 256>>>(feat, fhi, flo, (size_t)N * CC,
                               den, (size_t)N * HH, wv, (size_t)N * CC);

    GemmArgs a{};
    a.ldx = CC; a.kTot = CC; a.ldw = CC; a.w_y_off = 0; a.col_y = 0;
    a.bias_y_off = 0; a.ldo = CC; a.out_y_off = 0; a.M = N; a.nY = 1; a.doGelu = 0;

    // 1) q + k projections in one launch (grid.y=2)
    a.Ahi = fhi; a.Alo = flo;
    a.wOff = WOFF_Q; a.w_y_off = 16384; a.bias = bias_qk; a.bias_y_off = CC;
    a.outF = q; a.out_y_off = (size_t)N * CC; a.nY = 2;
    launch_gemm(a);
    a.w_y_off = 0; a.bias_y_off = 0; a.out_y_off = 0; a.nY = 1;

    // v projection -> fp16 hi/lo output
    a.wOff = WOFF_V; a.bias = bv; a.outF = nullptr;
    a.outHhi = vhi; a.outHlo = vlo;             launch_gemm(a);
    a.outHhi = nullptr; a.outHlo = nullptr;

    // 2) vt[t] = v @ W_rel[t], grid.y = 8
    a.Ahi = vhi; a.Alo = vlo;
    a.wOff = WOFF_REL; a.w_y_off = 16384; a.bias = nullptr;
    a.outF = vt; a.out_y_off = (size_t)N * CC; a.nY = TT;  launch_gemm(a);
    a.w_y_off = 0; a.out_y_off = 0; a.nY = 1;

    // 3) edge scores + denominators
    {
        long total = (long)E * HH;
        score_kernel<<<(int)((total + 255) / 256), 256>>>(q, k, src, dst, esc, den, E);
    }
    // 4) edge aggregation
    {
        long total = (long)E * 32;
        agg_kernel<<<(int)((total + 255) / 256), 256>>>(vt, efeat, esc, den,
                                                        src, dst, etype, wv, E, N);
    }

    // 5) feat1 = feat + wv @ Wproj + bproj  (fp32 A inline)
    a.Ahi = nullptr; a.Alo = nullptr; a.Xf = wv;
    a.wOff = WOFF_PROJ; a.bias = bproj; a.res = feat; a.outF = feat1;
    launch_gemm(a);
    a.res = nullptr;

    // 6) hn = layernorm(feat1) -> fp16 hi/lo
    {
        long total = (long)N * 32;
        ln_kernel<<<(int)((total + 255) / 256), 256>>>(feat1, ln_g, ln_b, hnhi, hnlo, N);
    }

    // 7) hmid = gelu(hn @ W1 + b1), grid.y = 4
    a.Xf = nullptr; a.Ahi = hnhi; a.Alo = hnlo;
    a.wOff = WOFF_W1; a.ldw = 4 * CC; a.col_y = 128; a.bias = b1;
    a.outF = hmid; a.ldo = 4 * CC; a.nY = 4; a.doGelu = 1;
    launch_gemm(a);
    a.col_y = 0; a.nY = 1; a.doGelu = 0;

    // 8) feat_out = feat1 + hmid @ W2 + b2  (fp32 A, K = 512)
    a.Ahi = nullptr; a.Alo = nullptr; a.Xf = hmid;
    a.ldx = 4 * CC; a.kTot = 4 * CC; a.wOff = WOFF_W2; a.ldw = CC;
    a.bias = b2; a.res = feat1; a.outF = out_feat; a.ldo = CC;
    launch_gemm(a);
    a.res = nullptr; a.ldx = CC; a.kTot = CC;

    // 9) efeat_out = efeat @ WeW + beW  (fp32 A, E rows)
    a.Xf = efeat; a.wOff = WOFF_EW; a.bias = beW;
    a.outF = out_efeat; a.M = E;
    launch_gemm(a);
}

// round 7
// speedup vs baseline: 3.0263x; 1.1157x over previous
#include <cuda_runtime.h>
#include <cuda_fp16.h>
#include <math.h>
#include <stdint.h>

// Problem constants
#define NN 50000
#define EE 800000
#define CC 128
#define HH 8
#define TT 8

// ---------------- scratch (device globals) -------------------------------------
__device__ float g_qk[(size_t)2 * NN * CC];          // q then k
__device__ __half g_v16[(size_t)NN * CC];
__device__ __half g_feat16[(size_t)NN * CC];
__device__ __half g_hn16[(size_t)NN * CC];
__device__ float g_vt[(size_t)TT * NN * CC];
__device__ float g_escore[(size_t)EE * HH];
__device__ float g_den[(size_t)NN * HH];
__device__ float g_wv[(size_t)NN * CC];
__device__ float g_feat1[(size_t)NN * CC];
__device__ float g_hmid[(size_t)NN * 4 * CC];
__device__ float g_bias_qkv[3 * CC];

// fp16 weights
#define WOFF_Q    0
#define WOFF_K    16384
#define WOFF_V    32768
#define WOFF_REL  49152
#define WOFF_PROJ 180224
#define WOFF_EW   196608
#define WOFF_W1   212992
#define WOFF_W2   278528
#define WBF_TOTAL 344064
__device__ __half g_wh[WBF_TOTAL];

// ---------------- helpers -----------------------------------------------------------
__device__ __forceinline__ uint32_t half2_u(__half2 v) {
    return *reinterpret_cast<uint32_t*>(&v);
}
__device__ __forceinline__ uint32_t smem_u32(const void* p) {
    uint32_t addr;
    asm("{ .reg .u64 t; cvta.to.shared.u64 t, %1; cvt.u32.u64 %0, t; }"
        : "=r"(addr) : "l"(p));
    return addr;
}
__device__ __forceinline__ void ldsm_x4(uint32_t* r, uint32_t addr) {
    asm volatile("ldmatrix.sync.aligned.m8n8.x4.shared.b16 {%0,%1,%2,%3}, [%4];"
                 : "=r"(r[0]), "=r"(r[1]), "=r"(r[2]), "=r"(r[3]) : "r"(addr));
}
__device__ __forceinline__ void ldsm_x4_t(uint32_t* r, uint32_t addr) {
    asm volatile("ldmatrix.sync.aligned.m8n8.x4.trans.shared.b16 {%0,%1,%2,%3}, [%4];"
                 : "=r"(r[0]), "=r"(r[1]), "=r"(r[2]), "=r"(r[3]) : "r"(addr));
}
__device__ __forceinline__ void mma16816(float* c, const uint32_t* a, const uint32_t* b) {
    asm volatile(
        "mma.sync.aligned.m16n8k16.row.col.f32.f16.f16.f32 "
        "{%0,%1,%2,%3}, {%4,%5,%6,%7}, {%8,%9}, {%0,%1,%2,%3};"
        : "+f"(c[0]), "+f"(c[1]), "+f"(c[2]), "+f"(c[3])
        : "r"(a[0]), "r"(a[1]), "r"(a[2]), "r"(a[3]), "r"(b[0]), "r"(b[1]));
}
__device__ __forceinline__ void cp16(uint32_t dst, const void* src) {
    asm volatile("cp.async.cg.shared.global [%0], [%1], 16;"
                 :: "r"(dst), "l"(src) : "memory");
}
__device__ __forceinline__ void cp16z(uint32_t dst, const void* src, int bytes) {
    asm volatile("cp.async.cg.shared.global [%0], [%1], 16, %2;"
                 :: "r"(dst), "l"(src), "r"(bytes) : "memory");
}
__device__ __forceinline__ void cp_commit() {
    asm volatile("cp.async.commit_group;" ::: "memory");
}
__device__ __forceinline__ void cp_wait2() {
    asm volatile("cp.async.wait_group 2;" ::: "memory");
}

// smem tile swizzles
// A tile: 128 rows x 32 k fp16, 64B rows
__device__ __forceinline__ uint32_t a_swz(int r, int c16) {
    return (uint32_t)r * 64u + (uint32_t)((c16 ^ ((r >> 1) & 3)) << 4);
}
// B tile: 32 k-rows x 128 n fp16, 256B rows
__device__ __forceinline__ uint32_t b_swz(int k, int c16) {
    return (uint32_t)k * 256u + (uint32_t)((c16 ^ (k & 7)) << 4);
}
__device__ __forceinline__ float gelu1(float v) {
    return 0.5f * v * (1.0f + erff(v * 0.70710678118654752f));
}

// ---------------- pipelined fp16 tensor-core GEMM ---------------------------------
// CTA tile 128x128, K-chunk 32, 4-stage cp.async pipeline (prefetch depth 3).
// Single-pass fp16: D = A16 @ B16 (fp32 accumulate).
// stage (16KB): A @0 (8KB), B @8K (8KB). 4 stages = 64KB.
#define NSTG 4
#define STG 16384
#define SA 0
#define SB 8192
#define SM_TOTAL 65536

__global__ void __launch_bounds__(256, 2) gemm_fp16_kernel(
    const float* __restrict__ Xf,                 // fp32 A (or null)
    const __half* __restrict__ Ah,                // fp16 A (or null)
    int ldx, int kTot,
    const __half* __restrict__ Bh,                // fp16 weights
    int ldw, size_t w_y_off, int col_y,
    const float* __restrict__ bias, int bias_y_off,
    const float* __restrict__ res,                // nullable, ld=128
    float* __restrict__ outF, int ldo, size_t out_y_off,
    __half* __restrict__ outH, int outH_y,        // fp16 out for blockIdx.y == outH_y
    int M, int doGelu)
{
    extern __shared__ char smem[];
    const uint32_t sb = smem_u32(smem);
    const int tid  = threadIdx.x;
    const int wid  = tid >> 5;
    const int lane = tid & 31;
    const int wm   = wid & 1;
    const int wn   = wid >> 1;
    const int row0  = blockIdx.x * 128;
    const int wcol0 = blockIdx.y * col_y;

    Bh += (size_t)blockIdx.y * w_y_off;
    if (outF) outF += (size_t)blockIdx.y * out_y_off;
    if (bias) bias += (size_t)blockIdx.y * bias_y_off;

    const bool aIsF32 = (Xf != nullptr);
    const int nCh = kTot >> 5;

    float acc[4][4][4];
#pragma unroll
    for (int i = 0; i < 4; i++)
#pragma unroll
        for (int j = 0; j < 4; j++)
#pragma unroll
            for (int l = 0; l < 4; l++) acc[i][j][l] = 0.0f;

    float4 ap[4];   // fp32-A prefetch registers

#define PREFETCH_B(kc, st) do {                                                    \
        uint32_t base = sb + (uint32_t)(st) * STG;                                 \
        _Pragma("unroll")                                                          \
        for (int i = 0; i < 2; i++) {                                              \
            int u = tid + i * 256;                                                 \
            int kk = u >> 4, c16 = u & 15;                                         \
            size_t gsrc = (size_t)((kc) * 32 + kk) * ldw + wcol0 + c16 * 8;        \
            cp16(base + SB + b_swz(kk, c16), Bh + gsrc);                           \
        }                                                                          \
    } while (0)

#define PREFETCH_A16(kc, st) do {                                                  \
        uint32_t base = sb + (uint32_t)(st) * STG;                                 \
        _Pragma("unroll")                                                          \
        for (int i = 0; i < 2; i++) {                                              \
            int u = tid + i * 256;                                                 \
            int r = u >> 2, c16 = u & 3;                                           \
            int row = row0 + r;                                                    \
            size_t gsrc = (size_t)row * ldx + (kc) * 32 + c16 * 8;                 \
            int bytes = (row < M) ? 16 : 0;                                        \
            cp16z(base + SA + a_swz(r, c16), Ah + gsrc, bytes);                    \
        }                                                                          \
    } while (0)

#define LDG_A(kc) do {                                                             \
        _Pragma("unroll")                                                          \
        for (int i = 0; i < 4; i++) {                                              \
            int u = tid + i * 256;                                                 \
            int r = u >> 3, c4 = u & 7;                                            \
            int row = row0 + r;                                                    \
            ap[i] = (row < M)                                                      \
                ? *(const float4*)&Xf[(size_t)row * ldx + (kc) * 32 + c4 * 4]      \
                : make_float4(0.f, 0.f, 0.f, 0.f);                                 \
        }                                                                          \
    } while (0)

#define STS_A(st) do {                                                             \
        _Pragma("unroll")                                                          \
        for (int i = 0; i < 4; i++) {                                              \
            int u = tid + i * 256;                                                 \
            int r = u >> 3, c4 = u & 7;                                            \
            __half2 h0 = __floats2half2_rn(ap[i].x, ap[i].y);                      \
            __half2 h1 = __floats2half2_rn(ap[i].z, ap[i].w);                      \
            uint32_t d = a_swz(r, c4 >> 1) + (uint32_t)((c4 & 1) << 3);            \
            *(uint2*)(smem + (st) * STG + SA + d)                                  \
                = make_uint2(half2_u(h0), half2_u(h1));                            \
        }                                                                          \
    } while (0)

    // ---- prologue: prefetch chunks 0..2 (3 groups) ----
#pragma unroll
    for (int c = 0; c < NSTG - 1; c++) {
        if (c < nCh) {
            PREFETCH_B(c, c);
            if (!aIsF32) PREFETCH_A16(c, c);
        }
        cp_commit();
    }
    if (aIsF32) LDG_A(0);

    // ldmatrix lane coordinates
    const int a_r  = wm * 64 + (lane & 15);
    const int a_k8 = (lane >> 4) << 3;
    const int b_k  = (((lane >> 3) & 1) << 3) + (lane & 7);
    const int b_n  = wn * 32 + ((lane >> 4) << 3);

    for (int kc = 0; kc < nCh; kc++) {
        const int s = kc & (NSTG - 1);
        const uint32_t base = sb + (uint32_t)s * STG;

        cp_wait2();                 // ensure chunk kc's group has landed
        if (aIsF32) STS_A(s);
        __syncthreads();

        {
            int pf = kc + NSTG - 1;
            if (pf < nCh) {
                PREFETCH_B(pf, pf & (NSTG - 1));
                if (!aIsF32) PREFETCH_A16(pf, pf & (NSTG - 1));
            }
            cp_commit();            // exactly one group per iteration
            if (aIsF32 && kc + 1 < nCh) LDG_A(kc + 1);
        }

#pragma unroll
        for (int ks = 0; ks < 2; ks++) {
            const int k0 = ks * 16;
            uint32_t bh[4][2];
            {
                int kk = k0 + b_k;
#pragma unroll
                for (int pair = 0; pair < 2; pair++) {
                    int n = b_n + pair * 16;
                    uint32_t addr = (uint32_t)kk * 256u
                        + (((uint32_t)(n * 2)) ^ (uint32_t)((kk & 7) << 4));
                    uint32_t r[4];
                    ldsm_x4_t(r, base + SB + addr);
                    bh[2 * pair][0] = r[0]; bh[2 * pair][1] = r[1];
                    bh[2 * pair + 1][0] = r[2]; bh[2 * pair + 1][1] = r[3];
                }
            }
            uint32_t a[4][4];
            {
                int kk = k0 + a_k8;
#pragma unroll
                for (int mf = 0; mf < 4; mf++)
                    ldsm_x4(a[mf], base + SA + a_swz(a_r + mf * 16, kk >> 3));
            }
#pragma unroll
            for (int mf = 0; mf < 4; mf++)
#pragma unroll
                for (int nf = 0; nf < 4; nf++)
                    mma16816(acc[mf][nf], a[mf], bh[nf]);
        }
    }

    // ---- epilogue ----
    const bool h16 = ((int)blockIdx.y == outH_y);
    const int g = lane >> 2;
    const int t = lane & 3;
#pragma unroll
    for (int mf = 0; mf < 4; mf++) {
#pragma unroll
        for (int nf = 0; nf < 4; nf++) {
            int cl = wn * 32 + nf * 8 + 2 * t;
            float b0 = 0.f, b1 = 0.f;
            if (bias) { b0 = bias[wcol0 + cl]; b1 = bias[wcol0 + cl + 1]; }
#pragma unroll
            for (int half = 0; half < 2; half++) {
                int r = row0 + wm * 64 + mf * 16 + g + half * 8;
                if (r >= M) continue;
                float v0 = acc[mf][nf][2 * half]     + b0;
                float v1 = acc[mf][nf][2 * half + 1] + b1;
                if (doGelu) { v0 = gelu1(v0); v1 = gelu1(v1); }
                if (res) {
                    float2 rv = *(const float2*)&res[(size_t)r * 128 + cl];
                    v0 += rv.x; v1 += rv.y;
                }
                if (h16) {
                    *(__half2*)&outH[(size_t)r * 128 + cl] = __floats2half2_rn(v0, v1);
                } else {
                    *(float2*)&outF[(size_t)r * ldo + wcol0 + cl] = make_float2(v0, v1);
                }
            }
        }
    }
#undef PREFETCH_B
#undef PREFETCH_A16
#undef LDG_A
#undef STS_A
}

// ---------------- weight conversion (once) -----------------------------------------
__global__ void conv_weights_kernel(
    const float* __restrict__ Wq, const float* __restrict__ Wk,
    const float* __restrict__ Wv, const float* __restrict__ Wrel,
    const float* __restrict__ Wproj, const float* __restrict__ Wew,
    const float* __restrict__ W1, const float* __restrict__ W2,
    const float* __restrict__ bq, const float* __restrict__ bk,
    const float* __restrict__ bv,
    __half* __restrict__ wh, float* __restrict__ bias_qkv)
{
    int i = blockIdx.x * blockDim.x + threadIdx.x;
    if (i < 3 * CC)
        bias_qkv[i] = (i < CC) ? bq[i] : (i < 2 * CC ? bk[i - CC] : bv[i - 2 * CC]);
    if (i >= WBF_TOTAL) return;
    float x;
    if (i < WOFF_K)           x = Wq[i];
    else if (i < WOFF_V)      x = Wk[i - WOFF_K];
    else if (i < WOFF_REL)    x = Wv[i - WOFF_V];
    else if (i < WOFF_PROJ)   x = Wrel[i - WOFF_REL];
    else if (i < WOFF_EW)     x = Wproj[i - WOFF_PROJ];
    else if (i < WOFF_W1)     x = Wew[i - WOFF_EW];
    else if (i < WOFF_W2)     x = W1[i - WOFF_W1];
    else                      x = W2[i - WOFF_W2];
    wh[i] = __float2half_rn(x);
}

// ---------------- fp32 -> fp16 + zero accumulators ------------------------------------
__global__ void prep_kernel(const float* __restrict__ x,
                            __half* __restrict__ h16, size_t n,
                            float* __restrict__ z1, size_t n1,
                            float* __restrict__ z2, size_t n2)
{
    size_t i = (size_t)blockIdx.x * blockDim.x + threadIdx.x;
    size_t stride = (size_t)gridDim.x * blockDim.x;
    for (size_t j = i; j < n; j += stride) h16[j] = __float2half_rn(x[j]);
    for (size_t j = i; j < n1; j += stride) z1[j] = 0.0f;
    for (size_t j = i; j < n2; j += stride) z2[j] = 0.0f;
}

// ---------------- edge scores + softmax denominators ----------------------------------
__global__ void score_kernel(
    const float* __restrict__ q, const float* __restrict__ k,
    const int* __restrict__ src, const int* __restrict__ dst,
    float* __restrict__ escore, float* __restrict__ den, int E)
{
    long idx = (long)blockIdx.x * blockDim.x + threadIdx.x;
    if (idx >= (long)E * HH) return;
    int e = (int)(idx >> 3);
    int h = (int)(idx & 7);
    int s = src[e], d = dst[e];
    const float4* qp = (const float4*)&q[(size_t)d * CC + h * 16];
    const float4* kp = (const float4*)&k[(size_t)s * CC + h * 16];
    float acc = 0.f;
#pragma unroll
    for (int i = 0; i < 4; i++) {
        float4 a = qp[i], b = kp[i];
        acc += a.x * b.x + a.y * b.y + a.z * b.z + a.w * b.w;
    }
    acc *= 0.25f;
    acc = fminf(fmaxf(acc, -10.0f), 10.0f);
    float ex = expf(acc);
    escore[idx] = ex;
    atomicAdd(&den[(size_t)d * HH + h], ex);
}

// ---------------- edge aggregation -----------------------------------------------------
__global__ void agg_kernel(
    const float* __restrict__ vt, const float* __restrict__ efeat,
    const float* __restrict__ escore, const float* __restrict__ den,
    const int* __restrict__ src, const int* __restrict__ dst,
    const int* __restrict__ etype,
    float* __restrict__ wv, int E, int Nn)
{
    int e = (int)(((long)blockIdx.x * blockDim.x + threadIdx.x) >> 5);
    if (e >= E) return;
    int lane = threadIdx.x & 31;
    int s = src[e], d = dst[e], t = etype[e];
    int h = lane >> 2;
    float alpha = escore[(size_t)e * HH + h] / den[(size_t)d * HH + h];
    float4 vv = *(const float4*)&vt[((size_t)t * Nn + s) * CC + lane * 4];
    float4 ef = *(const float4*)&efeat[(size_t)e * CC + lane * 4];
    float m0 = (vv.x - ef.x) * alpha;
    float m1 = (vv.y - ef.y) * alpha;
    float m2 = (vv.z - ef.z) * alpha;
    float m3 = (vv.w - ef.w) * alpha;
    float* p = &wv[(size_t)d * CC + lane * 4];
    asm volatile("red.global.add.v4.f32 [%0], {%1, %2, %3, %4};"
                 :: "l"(p), "f"(m0), "f"(m1), "f"(m2), "f"(m3) : "memory");
}

// ---------------- layernorm, emits fp16 ------------------------------------------------
__global__ void ln_kernel(
    const float* __restrict__ x, const float* __restrict__ g,
    const float* __restrict__ b, __half* __restrict__ oh, int M)
{
    int row = (int)(((long)blockIdx.x * blockDim.x + threadIdx.x) >> 5);
    if (row >= M) return;
    int lane = threadIdx.x & 31;
    float4 v = *(const float4*)&x[(size_t)row * CC + lane * 4];
    float s = v.x + v.y + v.z + v.w;
#pragma unroll
    for (int o = 16; o > 0; o >>= 1) s += __shfl_xor_sync(0xffffffffu, s, o);
    float mu = s * (1.0f / 128.0f);
    float d0 = v.x - mu, d1 = v.y - mu, d2 = v.z - mu, d3 = v.w - mu;
    float ss = d0 * d0 + d1 * d1 + d2 * d2 + d3 * d3;
#pragma unroll
    for (int o = 16; o > 0; o >>= 1) ss += __shfl_xor_sync(0xffffffffu, ss, o);
    float inv = rsqrtf(ss * (1.0f / 128.0f) + 1e-5f);
    float4 gg = *(const float4*)&g[lane * 4];
    float4 bb = *(const float4*)&b[lane * 4];
    __half2 h0 = __floats2half2_rn(d0 * inv * gg.x + bb.x, d1 * inv * gg.y + bb.y);
    __half2 h1 = __floats2half2_rn(d2 * inv * gg.z + bb.z, d3 * inv * gg.w + bb.w);
    size_t o = (size_t)row * CC + lane * 4;
    *(__half2*)&oh[o]     = h0;
    *(__half2*)&oh[o + 2] = h1;
}

// ---------------- host side --------------------------------------------------------------
struct GemmArgs {
    const float* Xf;
    const __half* Ah;
    int ldx, kTot;
    size_t wOff; int ldw; size_t w_y_off; int col_y;
    const float* bias; int bias_y_off; const float* res;
    float* outF; int ldo; size_t out_y_off;
    __half* outH; int outH_y;
    int M, nY, doGelu;
};

static __half* h_wh;

static inline void launch_gemm(const GemmArgs& a)
{
    dim3 grid((a.M + 127) / 128, a.nY);
    gemm_fp16_kernel<<<grid, 256, SM_TOTAL>>>(
        a.Xf, a.Ah, a.ldx, a.kTot,
        h_wh + a.wOff, a.ldw, a.w_y_off, a.col_y,
        a.bias, a.bias_y_off, a.res, a.outF, a.ldo, a.out_y_off,
        a.outH, a.outH_y, a.M, a.doGelu);
}

extern "C" void kernel_launch(void* const* d_in, const int* in_sizes, int n_in,
                              void* d_out, int out_size)
{
    const float* feat  = (const float*)d_in[0];
    const float* efeat = (const float*)d_in[1];
    const int*   src   = (const int*)d_in[2];
    const int*   dst   = (const int*)d_in[3];
    const int*   etype = (const int*)d_in[4];

    int base = 5;
    if (in_sizes[5] == 1) base = 6;

    const float* Wq    = (const float*)d_in[base + 0];
    const float* bq    = (const float*)d_in[base + 1];
    const float* Wk    = (const float*)d_in[base + 2];
    const float* bk    = (const float*)d_in[base + 3];
    const float* Wv    = (const float*)d_in[base + 4];
    const float* bv    = (const float*)d_in[base + 5];
    const float* W_rel = (const float*)d_in[base + 6];
    const float* Wproj = (const float*)d_in[base + 7];
    const float* bproj = (const float*)d_in[base + 8];
    const float* WeW   = (const float*)d_in[base + 9];
    const float* beW   = (const float*)d_in[base + 10];
    const float* ln_g  = (const float*)d_in[base + 11];
    const float* ln_b  = (const float*)d_in[base + 12];
    const float* W1    = (const float*)d_in[base + 13];
    const float* b1    = (const float*)d_in[base + 14];
    const float* W2    = (const float*)d_in[base + 15];
    const float* b2    = (const float*)d_in[base + 16];

    const int N = in_sizes[0] / CC;
    const int E = in_sizes[1] / CC;

    float *qk, *vt, *esc, *den, *wv, *feat1, *hmid, *bias_qkv;
    __half *v16, *f16, *hn16;
    cudaGetSymbolAddress((void**)&qk,    g_qk);
    cudaGetSymbolAddress((void**)&vt,    g_vt);
    cudaGetSymbolAddress((void**)&esc,   g_escore);
    cudaGetSymbolAddress((void**)&den,   g_den);
    cudaGetSymbolAddress((void**)&wv,    g_wv);
    cudaGetSymbolAddress((void**)&feat1, g_feat1);
    cudaGetSymbolAddress((void**)&hmid,  g_hmid);
    cudaGetSymbolAddress((void**)&bias_qkv, g_bias_qkv);
    cudaGetSymbolAddress((void**)&v16,   g_v16);
    cudaGetSymbolAddress((void**)&f16,   g_feat16);
    cudaGetSymbolAddress((void**)&hn16,  g_hn16);
    cudaGetSymbolAddress((void**)&h_wh,  g_wh);

    cudaFuncSetAttribute(gemm_fp16_kernel,
                         cudaFuncAttributeMaxDynamicSharedMemorySize, SM_TOTAL);

    float* out_feat  = (float*)d_out;
    float* out_efeat = (float*)d_out + (size_t)N * CC;
    float* q = qk;
    float* k = qk + (size_t)N * CC;

    // 0) one-time prep
    conv_weights_kernel<<<(WBF_TOTAL + 255) / 256, 256>>>(
        Wq, Wk, Wv, W_rel, Wproj, WeW, W1, W2, bq, bk, bv, h_wh, bias_qkv);
    prep_kernel<<<1024, 256>>>(feat, f16, (size_t)N * CC,
                               den, (size_t)N * HH, wv, (size_t)N * CC);

    GemmArgs a{};
    a.ldx = CC; a.kTot = CC; a.ldw = CC; a.w_y_off = 0; a.col_y = 0;
    a.bias_y_off = 0; a.ldo = CC; a.out_y_off = 0;
    a.outH = nullptr; a.outH_y = -1; a.M = N; a.nY = 1; a.doGelu = 0;

    // 1) fused q+k+v (grid.y = 3); y=0,1 -> fp32 q,k; y=2 -> fp16 v
    a.Ah = f16;
    a.wOff = WOFF_Q; a.w_y_off = 16384; a.bias = bias_qkv; a.bias_y_off = CC;
    a.outF = qk; a.out_y_off = (size_t)N * CC;
    a.outH = v16; a.outH_y = 2; a.nY = 3;
    launch_gemm(a);
    a.w_y_off = 0; a.bias_y_off = 0; a.out_y_off = 0;
    a.outH = nullptr; a.outH_y = -1; a.nY = 1;

    // 2) vt[t] = v @ W_rel[t], grid.y = 8
    a.Ah = v16;
    a.wOff = WOFF_REL; a.w_y_off = 16384; a.bias = nullptr;
    a.outF = vt; a.out_y_off = (size_t)N * CC; a.nY = TT;  launch_gemm(a);
    a.w_y_off = 0; a.out_y_off = 0; a.nY = 1;

    // 3) edge scores + denominators
    {
        long total = (long)E * HH;
        score_kernel<<<(int)((total + 255) / 256), 256>>>(q, k, src, dst, esc, den, E);
    }
    // 4) edge aggregation
    {
        long total = (long)E * 32;
        agg_kernel<<<(int)((total + 255) / 256), 256>>>(vt, efeat, esc, den,
                                                        src, dst, etype, wv, E, N);
    }

    // 5) feat1 = feat + wv @ Wproj + bproj  (fp32 A inline)
    a.Ah = nullptr; a.Xf = wv;
    a.wOff = WOFF_PROJ; a.bias = bproj; a.res = feat; a.outF = feat1;
    launch_gemm(a);
    a.res = nullptr;

    // 6) hn = layernorm(feat1) -> fp16
    {
        long total = (long)N * 32;
        ln_kernel<<<(int)((total + 255) / 256), 256>>>(feat1, ln_g, ln_b, hn16, N);
    }

    // 7) hmid = gelu(hn @ W1 + b1), grid.y = 4
    a.Xf = nullptr; a.Ah = hn16;
    a.wOff = WOFF_W1; a.ldw = 4 * CC; a.col_y = 128; a.bias = b1;
    a.outF = hmid; a.ldo = 4 * CC; a.nY = 4; a.doGelu = 1;
    launch_gemm(a);
    a.col_y = 0; a.nY = 1; a.doGelu = 0;

    // 8) feat_out = feat1 + hmid @ W2 + b2  (fp32 A, K = 512, 16-chunk pipeline)
    a.Ah = nullptr; a.Xf = hmid;
    a.ldx = 4 * CC; a.kTot = 4 * CC; a.wOff = WOFF_W2; a.ldw = CC;
    a.bias = b2; a.res = feat1; a.outF = out_feat; a.ldo = CC;
    launch_gemm(a);
    a.res = nullptr; a.ldx = CC; a.kTot = CC;

    // 9) efeat_out = efeat @ WeW + beW  (fp32 A, E rows)
    a.Xf = efeat; a.wOff = WOFF_EW; a.bias = beW;
    a.outF = out_efeat; a.M = E;
    launch_gemm(a);
}

// round 8
// speedup vs baseline: 3.1505x; 1.0410x over previous
#include <cuda_runtime.h>
#include <cuda_fp16.h>
#include <math.h>
#include <stdint.h>

// Problem constants
#define NN 50000
#define EE 800000
#define CC 128
#define HH 8
#define TT 8

// ---------------- scratch (device globals) -------------------------------------
__device__ float g_qk[(size_t)2 * NN * CC];          // q then k
__device__ __half g_v16[(size_t)NN * CC];
__device__ __half g_feat16[(size_t)NN * CC];
__device__ __half g_hn16[(size_t)NN * CC];
__device__ __half g_vt16[(size_t)TT * NN * CC];      // fp16 vt (102.4 MB)
__device__ __half g_hmid16[(size_t)NN * 4 * CC];     // fp16 hmid (51.2 MB)
__device__ float g_escore[(size_t)EE * HH];
__device__ float g_den[(size_t)NN * HH];
__device__ float g_wv[(size_t)NN * CC];
__device__ float g_feat1[(size_t)NN * CC];
__device__ float g_bias_qkv[3 * CC];

// fp16 weights
#define WOFF_Q    0
#define WOFF_K    16384
#define WOFF_V    32768
#define WOFF_REL  49152
#define WOFF_PROJ 180224
#define WOFF_EW   196608
#define WOFF_W1   212992
#define WOFF_W2   278528
#define WBF_TOTAL 344064
__device__ __half g_wh[WBF_TOTAL];

// ---------------- helpers -----------------------------------------------------------
__device__ __forceinline__ uint32_t half2_u(__half2 v) {
    return *reinterpret_cast<uint32_t*>(&v);
}
__device__ __forceinline__ uint32_t smem_u32(const void* p) {
    uint32_t addr;
    asm("{ .reg .u64 t; cvta.to.shared.u64 t, %1; cvt.u32.u64 %0, t; }"
        : "=r"(addr) : "l"(p));
    return addr;
}
__device__ __forceinline__ void ldsm_x4(uint32_t* r, uint32_t addr) {
    asm volatile("ldmatrix.sync.aligned.m8n8.x4.shared.b16 {%0,%1,%2,%3}, [%4];"
                 : "=r"(r[0]), "=r"(r[1]), "=r"(r[2]), "=r"(r[3]) : "r"(addr));
}
__device__ __forceinline__ void ldsm_x4_t(uint32_t* r, uint32_t addr) {
    asm volatile("ldmatrix.sync.aligned.m8n8.x4.trans.shared.b16 {%0,%1,%2,%3}, [%4];"
                 : "=r"(r[0]), "=r"(r[1]), "=r"(r[2]), "=r"(r[3]) : "r"(addr));
}
__device__ __forceinline__ void mma16816(float* c, const uint32_t* a, const uint32_t* b) {
    asm volatile(
        "mma.sync.aligned.m16n8k16.row.col.f32.f16.f16.f32 "
        "{%0,%1,%2,%3}, {%4,%5,%6,%7}, {%8,%9}, {%0,%1,%2,%3};"
        : "+f"(c[0]), "+f"(c[1]), "+f"(c[2]), "+f"(c[3])
        : "r"(a[0]), "r"(a[1]), "r"(a[2]), "r"(a[3]), "r"(b[0]), "r"(b[1]));
}
__device__ __forceinline__ void cp16(uint32_t dst, const void* src) {
    asm volatile("cp.async.cg.shared.global [%0], [%1], 16;"
                 :: "r"(dst), "l"(src) : "memory");
}
__device__ __forceinline__ void cp16z(uint32_t dst, const void* src, int bytes) {
    asm volatile("cp.async.cg.shared.global [%0], [%1], 16, %2;"
                 :: "r"(dst), "l"(src), "r"(bytes) : "memory");
}
__device__ __forceinline__ void cp_commit() {
    asm volatile("cp.async.commit_group;" ::: "memory");
}
__device__ __forceinline__ void cp_wait2() {
    asm volatile("cp.async.wait_group 2;" ::: "memory");
}

// smem tile swizzles
__device__ __forceinline__ uint32_t a_swz(int r, int c16) {
    return (uint32_t)r * 64u + (uint32_t)((c16 ^ ((r >> 1) & 3)) << 4);
}
__device__ __forceinline__ uint32_t b_swz(int k, int c16) {
    return (uint32_t)k * 256u + (uint32_t)((c16 ^ (k & 7)) << 4);
}
__device__ __forceinline__ float gelu1(float v) {
    return 0.5f * v * (1.0f + erff(v * 0.70710678118654752f));
}

// ---------------- pipelined fp16 tensor-core GEMM ---------------------------------
// CTA tile 128x128, K-chunk 32, 4-stage cp.async pipeline.
// halfMode: 0 = fp32 out; 1 = fp16 out only for blockIdx.y == outH_y (else fp32);
//           2 = fp16 out for all y (outH advanced by out_y_off per y).
#define NSTG 4
#define STG 16384
#define SA 0
#define SB 8192
#define SM_TOTAL 65536

__global__ void __launch_bounds__(256, 2) gemm_fp16_kernel(
    const float* __restrict__ Xf,                 // fp32 A (or null)
    const __half* __restrict__ Ah,                // fp16 A (or null)
    int ldx, int kTot,
    const __half* __restrict__ Bh,                // fp16 weights
    int ldw, size_t w_y_off, int col_y,
    const float* __restrict__ bias, int bias_y_off,
    const float* __restrict__ res,                // nullable, ld=128
    float* __restrict__ outF, int ldo, size_t out_y_off,
    __half* __restrict__ outH, int outH_y, int halfMode,
    int M, int doGelu)
{
    extern __shared__ char smem[];
    const uint32_t sb = smem_u32(smem);
    const int tid  = threadIdx.x;
    const int wid  = tid >> 5;
    const int lane = tid & 31;
    const int wm   = wid & 1;
    const int wn   = wid >> 1;
    const int row0  = blockIdx.x * 128;
    const int wcol0 = blockIdx.y * col_y;

    Bh += (size_t)blockIdx.y * w_y_off;
    if (outF) outF += (size_t)blockIdx.y * out_y_off;
    if (halfMode == 2) outH += (size_t)blockIdx.y * out_y_off;
    if (bias) bias += (size_t)blockIdx.y * bias_y_off;

    const bool aIsF32 = (Xf != nullptr);
    const int nCh = kTot >> 5;

    float acc[4][4][4];
#pragma unroll
    for (int i = 0; i < 4; i++)
#pragma unroll
        for (int j = 0; j < 4; j++)
#pragma unroll
            for (int l = 0; l < 4; l++) acc[i][j][l] = 0.0f;

    float4 ap[4];

#define PREFETCH_B(kc, st) do {                                                    \
        uint32_t base = sb + (uint32_t)(st) * STG;                                 \
        _Pragma("unroll")                                                          \
        for (int i = 0; i < 2; i++) {                                              \
            int u = tid + i * 256;                                                 \
            int kk = u >> 4, c16 = u & 15;                                         \
            size_t gsrc = (size_t)((kc) * 32 + kk) * ldw + wcol0 + c16 * 8;        \
            cp16(base + SB + b_swz(kk, c16), Bh + gsrc);                           \
        }                                                                          \
    } while (0)

#define PREFETCH_A16(kc, st) do {                                                  \
        uint32_t base = sb + (uint32_t)(st) * STG;                                 \
        _Pragma("unroll")                                                          \
        for (int i = 0; i < 2; i++) {                                              \
            int u = tid + i * 256;                                                 \
            int r = u >> 2, c16 = u & 3;                                           \
            int row = row0 + r;                                                    \
            size_t gsrc = (size_t)row * ldx + (kc) * 32 + c16 * 8;                 \
            int bytes = (row < M) ? 16 : 0;                                        \
            cp16z(base + SA + a_swz(r, c16), Ah + gsrc, bytes);                    \
        }                                                                          \
    } while (0)

#define LDG_A(kc) do {                                                             \
        _Pragma("unroll")                                                          \
        for (int i = 0; i < 4; i++) {                                              \
            int u = tid + i * 256;                                                 \
            int r = u >> 3, c4 = u & 7;                                            \
            int row = row0 + r;                                                    \
            ap[i] = (row < M)                                                      \
                ? *(const float4*)&Xf[(size_t)row * ldx + (kc) * 32 + c4 * 4]      \
                : make_float4(0.f, 0.f, 0.f, 0.f);                                 \
        }                                                                          \
    } while (0)

#define STS_A(st) do {                                                             \
        _Pragma("unroll")                                                          \
        for (int i = 0; i < 4; i++) {                                              \
            int u = tid + i * 256;                                                 \
            int r = u >> 3, c4 = u & 7;                                            \
            __half2 h0 = __floats2half2_rn(ap[i].x, ap[i].y);                      \
            __half2 h1 = __floats2half2_rn(ap[i].z, ap[i].w);                      \
            uint32_t d = a_swz(r, c4 >> 1) + (uint32_t)((c4 & 1) << 3);            \
            *(uint2*)(smem + (st) * STG + SA + d)                                  \
                = make_uint2(half2_u(h0), half2_u(h1));                            \
        }                                                                          \
    } while (0)

    // ---- prologue ----
#pragma unroll
    for (int c = 0; c < NSTG - 1; c++) {
        if (c < nCh) {
            PREFETCH_B(c, c);
            if (!aIsF32) PREFETCH_A16(c, c);
        }
        cp_commit();
    }
    if (aIsF32) LDG_A(0);

    const int a_r  = wm * 64 + (lane & 15);
    const int a_k8 = (lane >> 4) << 3;
    const int b_k  = (((lane >> 3) & 1) << 3) + (lane & 7);
    const int b_n  = wn * 32 + ((lane >> 4) << 3);

    for (int kc = 0; kc < nCh; kc++) {
        const int s = kc & (NSTG - 1);
        const uint32_t base = sb + (uint32_t)s * STG;

        cp_wait2();
        if (aIsF32) STS_A(s);
        __syncthreads();

        {
            int pf = kc + NSTG - 1;
            if (pf < nCh) {
                PREFETCH_B(pf, pf & (NSTG - 1));
                if (!aIsF32) PREFETCH_A16(pf, pf & (NSTG - 1));
            }
            cp_commit();
            if (aIsF32 && kc + 1 < nCh) LDG_A(kc + 1);
        }

#pragma unroll
        for (int ks = 0; ks < 2; ks++) {
            const int k0 = ks * 16;
            uint32_t bh[4][2];
            {
                int kk = k0 + b_k;
#pragma unroll
                for (int pair = 0; pair < 2; pair++) {
                    int n = b_n + pair * 16;
                    uint32_t addr = (uint32_t)kk * 256u
                        + (((uint32_t)(n * 2)) ^ (uint32_t)((kk & 7) << 4));
                    uint32_t r[4];
                    ldsm_x4_t(r, base + SB + addr);
                    bh[2 * pair][0] = r[0]; bh[2 * pair][1] = r[1];
                    bh[2 * pair + 1][0] = r[2]; bh[2 * pair + 1][1] = r[3];
                }
            }
            uint32_t a[4][4];
            {
                int kk = k0 + a_k8;
#pragma unroll
                for (int mf = 0; mf < 4; mf++)
                    ldsm_x4(a[mf], base + SA + a_swz(a_r + mf * 16, kk >> 3));
            }
#pragma unroll
            for (int mf = 0; mf < 4; mf++)
#pragma unroll
                for (int nf = 0; nf < 4; nf++)
                    mma16816(acc[mf][nf], a[mf], bh[nf]);
        }
    }

    // ---- epilogue ----
    const bool h16 = (halfMode == 2) || (halfMode == 1 && (int)blockIdx.y == outH_y);
    const int g = lane >> 2;
    const int t = lane & 3;
#pragma unroll
    for (int mf = 0; mf < 4; mf++) {
#pragma unroll
        for (int nf = 0; nf < 4; nf++) {
            int cl = wn * 32 + nf * 8 + 2 * t;
            float b0 = 0.f, b1 = 0.f;
            if (bias) { b0 = bias[wcol0 + cl]; b1 = bias[wcol0 + cl + 1]; }
#pragma unroll
            for (int half = 0; half < 2; half++) {
                int r = row0 + wm * 64 + mf * 16 + g + half * 8;
                if (r >= M) continue;
                float v0 = acc[mf][nf][2 * half]     + b0;
                float v1 = acc[mf][nf][2 * half + 1] + b1;
                if (doGelu) { v0 = gelu1(v0); v1 = gelu1(v1); }
                if (res) {
                    float2 rv = *(const float2*)&res[(size_t)r * 128 + cl];
                    v0 += rv.x; v1 += rv.y;
                }
                if (h16) {
                    *(__half2*)&outH[(size_t)r * ldo + wcol0 + cl]
                        = __floats2half2_rn(v0, v1);
                } else {
                    *(float2*)&outF[(size_t)r * ldo + wcol0 + cl] = make_float2(v0, v1);
                }
            }
        }
    }
#undef PREFETCH_B
#undef PREFETCH_A16
#undef LDG_A
#undef STS_A
}

// ---------------- weight conversion (once) -----------------------------------------
__global__ void conv_weights_kernel(
    const float* __restrict__ Wq, const float* __restrict__ Wk,
    const float* __restrict__ Wv, const float* __restrict__ Wrel,
    const float* __restrict__ Wproj, const float* __restrict__ Wew,
    const float* __restrict__ W1, const float* __restrict__ W2,
    const float* __restrict__ bq, const float* __restrict__ bk,
    const float* __restrict__ bv,
    __half* __restrict__ wh, float* __restrict__ bias_qkv)
{
    int i = blockIdx.x * blockDim.x + threadIdx.x;
    if (i < 3 * CC)
        bias_qkv[i] = (i < CC) ? bq[i] : (i < 2 * CC ? bk[i - CC] : bv[i - 2 * CC]);
    if (i >= WBF_TOTAL) return;
    float x;
    if (i < WOFF_K)           x = Wq[i];
    else if (i < WOFF_V)      x = Wk[i - WOFF_K];
    else if (i < WOFF_REL)    x = Wv[i - WOFF_V];
    else if (i < WOFF_PROJ)   x = Wrel[i - WOFF_REL];
    else if (i < WOFF_EW)     x = Wproj[i - WOFF_PROJ];
    else if (i < WOFF_W1)     x = Wew[i - WOFF_EW];
    else if (i < WOFF_W2)     x = W1[i - WOFF_W1];
    else                      x = W2[i - WOFF_W2];
    wh[i] = __float2half_rn(x);
}

// ---------------- fp32 -> fp16 + zero accumulators ------------------------------------
__global__ void prep_kernel(const float* __restrict__ x,
                            __half* __restrict__ h16, size_t n,
                            float* __restrict__ z1, size_t n1,
                            float* __restrict__ z2, size_t n2)
{
    size_t i = (size_t)blockIdx.x * blockDim.x + threadIdx.x;
    size_t stride = (size_t)gridDim.x * blockDim.x;
    for (size_t j = i; j < n; j += stride) h16[j] = __float2half_rn(x[j]);
    for (size_t j = i; j < n1; j += stride) z1[j] = 0.0f;
    for (size_t j = i; j < n2; j += stride) z2[j] = 0.0f;
}

// ---------------- edge scores + softmax denominators ----------------------------------
__global__ void score_kernel(
    const float* __restrict__ q, const float* __restrict__ k,
    const int* __restrict__ src, const int* __restrict__ dst,
    float* __restrict__ escore, float* __restrict__ den, int E)
{
    long idx = (long)blockIdx.x * blockDim.x + threadIdx.x;
    if (idx >= (long)E * HH) return;
    int e = (int)(idx >> 3);
    int h = (int)(idx & 7);
    int s = src[e], d = dst[e];
    const float4* qp = (const float4*)&q[(size_t)d * CC + h * 16];
    const float4* kp = (const float4*)&k[(size_t)s * CC + h * 16];
    float acc = 0.f;
#pragma unroll
    for (int i = 0; i < 4; i++) {
        float4 a = qp[i], b = kp[i];
        acc += a.x * b.x + a.y * b.y + a.z * b.z + a.w * b.w;
    }
    acc *= 0.25f;
    acc = fminf(fmaxf(acc, -10.0f), 10.0f);
    float ex = expf(acc);
    escore[idx] = ex;
    atomicAdd(&den[(size_t)d * HH + h], ex);
}

// ---------------- edge aggregation (vt fp16) -------------------------------------------
__global__ void agg_kernel(
    const __half* __restrict__ vt, const float* __restrict__ efeat,
    const float* __restrict__ escore, const float* __restrict__ den,
    const int* __restrict__ src, const int* __restrict__ dst,
    const int* __restrict__ etype,
    float* __restrict__ wv, int E, int Nn)
{
    int e = (int)(((long)blockIdx.x * blockDim.x + threadIdx.x) >> 5);
    if (e >= E) return;
    int lane = threadIdx.x & 31;
    int s = src[e], d = dst[e], t = etype[e];
    int h = lane >> 2;
    float alpha = escore[(size_t)e * HH + h] / den[(size_t)d * HH + h];
    uint2 raw = *(const uint2*)&vt[((size_t)t * Nn + s) * CC + lane * 4];
    __half2 v01 = *reinterpret_cast<__half2*>(&raw.x);
    __half2 v23 = *reinterpret_cast<__half2*>(&raw.y);
    float2 f01 = __half22float2(v01);
    float2 f23 = __half22float2(v23);
    float4 ef = *(const float4*)&efeat[(size_t)e * CC + lane * 4];
    float m0 = (f01.x - ef.x) * alpha;
    float m1 = (f01.y - ef.y) * alpha;
    float m2 = (f23.x - ef.z) * alpha;
    float m3 = (f23.y - ef.w) * alpha;
    float* p = &wv[(size_t)d * CC + lane * 4];
    asm volatile("red.global.add.v4.f32 [%0], {%1, %2, %3, %4};"
                 :: "l"(p), "f"(m0), "f"(m1), "f"(m2), "f"(m3) : "memory");
}

// ---------------- layernorm, emits fp16 ------------------------------------------------
__global__ void ln_kernel(
    const float* __restrict__ x, const float* __restrict__ g,
    const float* __restrict__ b, __half* __restrict__ oh, int M)
{
    int row = (int)(((long)blockIdx.x * blockDim.x + threadIdx.x) >> 5);
    if (row >= M) return;
    int lane = threadIdx.x & 31;
    float4 v = *(const float4*)&x[(size_t)row * CC + lane * 4];
    float s = v.x + v.y + v.z + v.w;
#pragma unroll
    for (int o = 16; o > 0; o >>= 1) s += __shfl_xor_sync(0xffffffffu, s, o);
    float mu = s * (1.0f / 128.0f);
    float d0 = v.x - mu, d1 = v.y - mu, d2 = v.z - mu, d3 = v.w - mu;
    float ss = d0 * d0 + d1 * d1 + d2 * d2 + d3 * d3;
#pragma unroll
    for (int o = 16; o > 0; o >>= 1) ss += __shfl_xor_sync(0xffffffffu, ss, o);
    float inv = rsqrtf(ss * (1.0f / 128.0f) + 1e-5f);
    float4 gg = *(const float4*)&g[lane * 4];
    float4 bb = *(const float4*)&b[lane * 4];
    __half2 h0 = __floats2half2_rn(d0 * inv * gg.x + bb.x, d1 * inv * gg.y + bb.y);
    __half2 h1 = __floats2half2_rn(d2 * inv * gg.z + bb.z, d3 * inv * gg.w + bb.w);
    size_t o = (size_t)row * CC + lane * 4;
    *(__half2*)&oh[o]     = h0;
    *(__half2*)&oh[o + 2] = h1;
}

// ---------------- host side --------------------------------------------------------------
struct GemmArgs {
    const float* Xf;
    const __half* Ah;
    int ldx, kTot;
    size_t wOff; int ldw; size_t w_y_off; int col_y;
    const float* bias; int bias_y_off; const float* res;
    float* outF; int ldo; size_t out_y_off;
    __half* outH; int outH_y; int halfMode;
    int M, nY, doGelu;
};

static __half* h_wh;

static inline void launch_gemm(const GemmArgs& a)
{
    dim3 grid((a.M + 127) / 128, a.nY);
    gemm_fp16_kernel<<<grid, 256, SM_TOTAL>>>(
        a.Xf, a.Ah, a.ldx, a.kTot,
        h_wh + a.wOff, a.ldw, a.w_y_off, a.col_y,
        a.bias, a.bias_y_off, a.res, a.outF, a.ldo, a.out_y_off,
        a.outH, a.outH_y, a.halfMode, a.M, a.doGelu);
}

extern "C" void kernel_launch(void* const* d_in, const int* in_sizes, int n_in,
                              void* d_out, int out_size)
{
    const float* feat  = (const float*)d_in[0];
    const float* efeat = (const float*)d_in[1];
    const int*   src   = (const int*)d_in[2];
    const int*   dst   = (const int*)d_in[3];
    const int*   etype = (const int*)d_in[4];

    int base = 5;
    if (in_sizes[5] == 1) base = 6;

    const float* Wq    = (const float*)d_in[base + 0];
    const float* bq    = (const float*)d_in[base + 1];
    const float* Wk    = (const float*)d_in[base + 2];
    const float* bk    = (const float*)d_in[base + 3];
    const float* Wv    = (const float*)d_in[base + 4];
    const float* bv    = (const float*)d_in[base + 5];
    const float* W_rel = (const float*)d_in[base + 6];
    const float* Wproj = (const float*)d_in[base + 7];
    const float* bproj = (const float*)d_in[base + 8];
    const float* WeW   = (const float*)d_in[base + 9];
    const float* beW   = (const float*)d_in[base + 10];
    const float* ln_g  = (const float*)d_in[base + 11];
    const float* ln_b  = (const float*)d_in[base + 12];
    const float* W1    = (const float*)d_in[base + 13];
    const float* b1    = (const float*)d_in[base + 14];
    const float* W2    = (const float*)d_in[base + 15];
    const float* b2    = (const float*)d_in[base + 16];

    const int N = in_sizes[0] / CC;
    const int E = in_sizes[1] / CC;

    float *qk, *esc, *den, *wv, *feat1, *bias_qkv;
    __half *v16, *f16, *hn16, *vt16, *hmid16;
    cudaGetSymbolAddress((void**)&qk,     g_qk);
    cudaGetSymbolAddress((void**)&esc,    g_escore);
    cudaGetSymbolAddress((void**)&den,    g_den);
    cudaGetSymbolAddress((void**)&wv,     g_wv);
    cudaGetSymbolAddress((void**)&feat1,  g_feat1);
    cudaGetSymbolAddress((void**)&bias_qkv, g_bias_qkv);
    cudaGetSymbolAddress((void**)&v16,    g_v16);
    cudaGetSymbolAddress((void**)&f16,    g_feat16);
    cudaGetSymbolAddress((void**)&hn16,   g_hn16);
    cudaGetSymbolAddress((void**)&vt16,   g_vt16);
    cudaGetSymbolAddress((void**)&hmid16, g_hmid16);
    cudaGetSymbolAddress((void**)&h_wh,   g_wh);

    cudaFuncSetAttribute(gemm_fp16_kernel,
                         cudaFuncAttributeMaxDynamicSharedMemorySize, SM_TOTAL);

    float* out_feat  = (float*)d_out;
    float* out_efeat = (float*)d_out + (size_t)N * CC;
    float* q = qk;
    float* k = qk + (size_t)N * CC;

    // 0) one-time prep
    conv_weights_kernel<<<(WBF_TOTAL + 255) / 256, 256>>>(
        Wq, Wk, Wv, W_rel, Wproj, WeW, W1, W2, bq, bk, bv, h_wh, bias_qkv);
    prep_kernel<<<1024, 256>>>(feat, f16, (size_t)N * CC,
                               den, (size_t)N * HH, wv, (size_t)N * CC);

    GemmArgs a{};
    a.ldx = CC; a.kTot = CC; a.ldw = CC; a.w_y_off = 0; a.col_y = 0;
    a.bias_y_off = 0; a.ldo = CC; a.out_y_off = 0;
    a.outH = nullptr; a.outH_y = -1; a.halfMode = 0;
    a.M = N; a.nY = 1; a.doGelu = 0;

    // 1) fused q+k+v (grid.y = 3); y=0,1 -> fp32 q,k; y=2 -> fp16 v16
    a.Ah = f16;
    a.wOff = WOFF_Q; a.w_y_off = 16384; a.bias = bias_qkv; a.bias_y_off = CC;
    a.outF = qk; a.out_y_off = (size_t)N * CC;
    a.outH = v16; a.outH_y = 2; a.halfMode = 1; a.nY = 3;
    launch_gemm(a);
    a.w_y_off = 0; a.bias_y_off = 0; a.out_y_off = 0;
    a.outH = nullptr; a.outH_y = -1; a.halfMode = 0; a.nY = 1;

    // 2) vt16[t] = v @ W_rel[t], grid.y = 8, fp16 out
    a.Ah = v16;
    a.wOff = WOFF_REL; a.w_y_off = 16384; a.bias = nullptr;
    a.outF = nullptr; a.outH = vt16; a.halfMode = 2;
    a.out_y_off = (size_t)N * CC; a.nY = TT;
    launch_gemm(a);
    a.w_y_off = 0; a.out_y_off = 0; a.outH = nullptr; a.halfMode = 0; a.nY = 1;

    // 3) edge scores + denominators
    {
        long total = (long)E * HH;
        score_kernel<<<(int)((total + 255) / 256), 256>>>(q, k, src, dst, esc, den, E);
    }
    // 4) edge aggregation (fp16 vt gather)
    {
        long total = (long)E * 32;
        agg_kernel<<<(int)((total + 255) / 256), 256>>>(vt16, efeat, esc, den,
                                                        src, dst, etype, wv, E, N);
    }

    // 5) feat1 = feat + wv @ Wproj + bproj  (fp32 A inline)
    a.Ah = nullptr; a.Xf = wv;
    a.wOff = WOFF_PROJ; a.bias = bproj; a.res = feat; a.outF = feat1;
    launch_gemm(a);
    a.res = nullptr;

    // 6) hn = layernorm(feat1) -> fp16
    {
        long total = (long)N * 32;
        ln_kernel<<<(int)((total + 255) / 256), 256>>>(feat1, ln_g, ln_b, hn16, N);
    }

    // 7) hmid16 = gelu(hn @ W1 + b1), grid.y = 4, fp16 out
    a.Xf = nullptr; a.Ah = hn16;
    a.wOff = WOFF_W1; a.ldw = 4 * CC; a.col_y = 128; a.bias = b1;
    a.outF = nullptr; a.outH = hmid16; a.halfMode = 2;
    a.ldo = 4 * CC; a.out_y_off = 0; a.nY = 4; a.doGelu = 1;
    launch_gemm(a);
    a.col_y = 0; a.outH = nullptr; a.halfMode = 0; a.nY = 1; a.doGelu = 0;

    // 8) feat_out = feat1 + hmid16 @ W2 + b2  (fp16 A, K = 512)
    a.Ah = hmid16; a.Xf = nullptr;
    a.ldx = 4 * CC; a.kTot = 4 * CC; a.wOff = WOFF_W2; a.ldw = CC;
    a.bias = b2; a.res = feat1; a.outF = out_feat; a.ldo = CC;
    launch_gemm(a);
    a.res = nullptr; a.ldx = CC; a.kTot = CC;

    // 9) efeat_out = efeat @ WeW + beW  (fp32 A, E rows)
    a.Ah = nullptr; a.Xf = efeat; a.wOff = WOFF_EW; a.bias = beW;
    a.outF = out_efeat; a.M = E;
    launch_gemm(a);
}